// round 1
// baseline (speedup 1.0000x reference)
#include <cuda_runtime.h>
#include <math.h>

#define B 4
#define S 2048
#define DM 128
#define H 8
#define DI 1024

// Scratch (static __device__ — no allocation)
__device__ float g_q[B*H*S*DM];
__device__ float g_k[B*H*S*DM];
__device__ float g_v[B*H*S*DM];
__device__ float g_attn[B*H*S*DM];

// ------------------------------------------------------------------
// Accurate sincos for args up to ~2100 rad: double-assisted range
// reduction + fp32 minimax polys. Immune to --use_fast_math.
// ------------------------------------------------------------------
__device__ __forceinline__ void sincos_acc(float x, float* so, float* co) {
    double td = (double)x;
    double qd = td * 0.63661977236758138;      // 2/pi
    int qi = __double2int_rn(qd);
    float r = (float)(td - (double)qi * 1.5707963267948966);
    float r2 = r * r;
    // sin on [-pi/4, pi/4]
    float sp = fmaf(r2, -1.9840874e-4f, 8.3333310e-3f);
    sp = fmaf(r2, sp, -1.6666667e-1f);
    sp = fmaf(r * r2, sp, r);
    // cos on [-pi/4, pi/4]
    float cp = fmaf(r2, 2.4760495e-5f, -1.3888397e-3f);
    cp = fmaf(r2, cp, 4.16666418e-2f);
    cp = fmaf(r2, cp, -0.5f);
    cp = fmaf(r2, cp, 1.0f);
    int n = qi & 3;
    float s = sp, c = cp;
    if (n & 1) { float t = s; s = c; c = -t; }
    if (n & 2) { s = -s; c = -c; }
    *so = s; *co = c;
}

// ------------------------------------------------------------------
// Kernel 1: QKV projection (X[8192,128] @ W[128,1024] + b) + RoPE,
// scattered into [B,H,S,128] scratch. blockIdx.z selects q/k/v.
// ------------------------------------------------------------------
__global__ __launch_bounds__(256) void qkv_kernel(
    const float* __restrict__ xq, const float* __restrict__ xk, const float* __restrict__ xv,
    const float* __restrict__ Wq, const float* __restrict__ bq,
    const float* __restrict__ Wk, const float* __restrict__ bk,
    const float* __restrict__ Wv, const float* __restrict__ bv)
{
    const int which = blockIdx.z;
    const float* X    = (which == 0) ? xq : (which == 1) ? xk : xv;
    const float* W    = (which == 0) ? Wq : (which == 1) ? Wk : Wv;
    const float* bias = (which == 0) ? bq : (which == 1) ? bk : bv;
    float* OUT        = (which == 0) ? g_q : (which == 1) ? g_k : g_v;

    extern __shared__ float sm[];
    float* xs = sm;              // [64][132]
    float* ws = sm + 64 * 132;   // [64][132]  transposed: ws[c][k]

    const int tid = threadIdx.x;
    const int gr0 = (int)blockIdx.y * 64;   // row tile 0..127
    const int gc0 = (int)blockIdx.x * 64;   // col tile 0..15

    #pragma unroll
    for (int i = 0; i < 8; i++) {
        int v = tid + i * 256;
        int row = v >> 5, c4 = (v & 31) << 2;
        *(float4*)&xs[row * 132 + c4] = *(const float4*)&X[(size_t)(gr0 + row) * DM + c4];
    }
    #pragma unroll
    for (int i = 0; i < 8; i++) {
        int v = tid + i * 256;
        int k = v >> 4, c = (v & 15) << 2;
        float4 t = *(const float4*)&W[(size_t)k * DI + gc0 + c];
        ws[(c + 0) * 132 + k] = t.x;
        ws[(c + 1) * 132 + k] = t.y;
        ws[(c + 2) * 132 + k] = t.z;
        ws[(c + 3) * 132 + k] = t.w;
    }
    __syncthreads();

    const int r0 = (tid >> 4) << 2;
    const int c0 = (tid & 15) << 2;

    float acc[4][4];
    #pragma unroll
    for (int i = 0; i < 4; i++)
        #pragma unroll
        for (int j = 0; j < 4; j++) acc[i][j] = 0.f;

    #pragma unroll 8
    for (int kk = 0; kk < 128; kk += 4) {
        float4 a[4], b[4];
        #pragma unroll
        for (int i = 0; i < 4; i++) a[i] = *(const float4*)&xs[(r0 + i) * 132 + kk];
        #pragma unroll
        for (int j = 0; j < 4; j++) b[j] = *(const float4*)&ws[(c0 + j) * 132 + kk];
        #pragma unroll
        for (int i = 0; i < 4; i++)
            #pragma unroll
            for (int j = 0; j < 4; j++)
                acc[i][j] = fmaf(a[i].x, b[j].x, fmaf(a[i].y, b[j].y,
                            fmaf(a[i].z, b[j].z, fmaf(a[i].w, b[j].w, acc[i][j]))));
    }

    const int gc = gc0 + c0;          // 4 consecutive cols, 4-aligned (even)
    const int hh = gc >> 7;
    const int d0 = gc & 127;
    float b0 = bias[gc], b1 = bias[gc + 1], b2 = bias[gc + 2], b3 = bias[gc + 3];

    float invf0 = 0.f, invf1 = 0.f;
    if (which < 2) {
        const double c13 = 13.287712379549449 / 128.0;  // log2(10000)/128
        invf0 = (float)exp2(-(double)(d0)     * c13);
        invf1 = (float)exp2(-(double)(d0 + 2) * c13);
    }

    #pragma unroll
    for (int i = 0; i < 4; i++) {
        int gr = gr0 + r0 + i;
        int bb = gr >> 11;
        int ss = gr & 2047;
        float v0 = acc[i][0] + b0;
        float v1 = acc[i][1] + b1;
        float v2 = acc[i][2] + b2;
        float v3 = acc[i][3] + b3;
        if (which < 2) {
            float th0 = (float)ss * invf0;   // matches jax fp32 product
            float th1 = (float)ss * invf1;
            float s0, cc0, s1, cc1;
            sincos_acc(th0, &s0, &cc0);
            sincos_acc(th1, &s1, &cc1);
            float o0 = v0 * cc0 - v1 * s0;
            float o1 = v1 * cc0 + v0 * s0;
            float o2 = v2 * cc1 - v3 * s1;
            float o3 = v3 * cc1 + v2 * s1;
            v0 = o0; v1 = o1; v2 = o2; v3 = o3;
        }
        *(float4*)&OUT[(((size_t)(bb * H + hh)) * S + ss) * DM + d0] =
            make_float4(v0, v1, v2, v3);
    }
}

// ------------------------------------------------------------------
// Kernel 2: causal flash attention. BM=128 q-rows/block, BN=64 keys
// per tile, 512 threads. Thread owns q-row r=tid>>2; col-group /
// d-group selected by tid&3. Online softmax in natural units.
// ------------------------------------------------------------------
#define BM 128
#define BN 64
#define QS 132
#define PSS 65
#define ATTN_SMEM ((BM*QS + BN*QS + BN*QS + BM*PSS) * 4)

__global__ __launch_bounds__(512, 1) void attn_kernel()
{
    extern __shared__ float sm[];
    float* qs = sm;                 // [128][132]
    float* ks = qs + BM * QS;       // [64][132]
    float* vs = ks + BN * QS;       // [64][132]
    float* ps = vs + BN * QS;       // [128][65]

    const int tid = threadIdx.x;
    const int bh  = blockIdx.y;
    const int qt  = (int)gridDim.x - 1 - (int)blockIdx.x;  // longest blocks first

    const float* Qb = g_q + ((size_t)bh * S + (size_t)qt * BM) * DM;
    const float* Kb = g_k + (size_t)bh * S * DM;
    const float* Vb = g_v + (size_t)bh * S * DM;

    #pragma unroll
    for (int i = 0; i < 8; i++) {
        int v = tid + i * 512;
        int row = v >> 5, c4 = (v & 31) << 2;
        *(float4*)&qs[row * QS + c4] = *(const float4*)&Qb[(size_t)row * DM + c4];
    }

    const int r  = tid >> 2;
    const int cg = tid & 3;
    const int c0 = cg << 4;       // score col group (16 cols)
    const int d0 = cg << 5;       // output d group (32 dims)
    const int qglob = qt * BM + r;

    float acc[32];
    #pragma unroll
    for (int i = 0; i < 32; i++) acc[i] = 0.f;
    float m = -1e30f, l = 0.f;

    const int nkt = 2 * qt + 2;
    for (int kt = 0; kt < nkt; kt++) {
        __syncthreads();
        #pragma unroll
        for (int i = 0; i < 4; i++) {
            int v = tid + i * 512;
            int row = v >> 5, c4 = (v & 31) << 2;
            *(float4*)&ks[row * QS + c4] =
                *(const float4*)&Kb[((size_t)kt * BN + row) * DM + c4];
            *(float4*)&vs[row * QS + c4] =
                *(const float4*)&Vb[((size_t)kt * BN + row) * DM + c4];
        }
        __syncthreads();

        float sc[16];
        #pragma unroll
        for (int j = 0; j < 16; j++) sc[j] = 0.f;
        #pragma unroll 4
        for (int kk = 0; kk < 128; kk += 4) {
            float4 q4 = *(const float4*)&qs[r * QS + kk];
            #pragma unroll
            for (int j = 0; j < 16; j++) {
                float4 k4 = *(const float4*)&ks[(c0 + j) * QS + kk];
                sc[j] = fmaf(q4.x, k4.x, fmaf(q4.y, k4.y,
                        fmaf(q4.z, k4.z, fmaf(q4.w, k4.w, sc[j]))));
            }
        }
        const float SCL = 0.088388347648318447f;  // 1/sqrt(128)
        #pragma unroll
        for (int j = 0; j < 16; j++) sc[j] *= SCL;
        if (kt >= 2 * qt) {                        // only diagonal tiles need mask
            int kb = kt * BN + c0;
            #pragma unroll
            for (int j = 0; j < 16; j++)
                if (kb + j > qglob) sc[j] = -1e30f;
        }

        float mt = sc[0];
        #pragma unroll
        for (int j = 1; j < 16; j++) mt = fmaxf(mt, sc[j]);
        mt = fmaxf(mt, __shfl_xor_sync(0xffffffffu, mt, 1));
        mt = fmaxf(mt, __shfl_xor_sync(0xffffffffu, mt, 2));
        float mnew = fmaxf(m, mt);
        float corr = __expf(m - mnew);
        m = mnew;
        l *= corr;
        #pragma unroll
        for (int i = 0; i < 32; i++) acc[i] *= corr;
        float lsum = 0.f;
        #pragma unroll
        for (int j = 0; j < 16; j++) {
            float p = __expf(sc[j] - mnew);
            lsum += p;
            ps[r * PSS + c0 + j] = p;
        }
        l += lsum;
        __syncthreads();

        #pragma unroll 2
        for (int c = 0; c < BN; c++) {
            float p = ps[r * PSS + c];
            const float4* vrow = (const float4*)&vs[c * QS + d0];
            #pragma unroll
            for (int j = 0; j < 8; j++) {
                float4 v4 = vrow[j];
                acc[4 * j + 0] = fmaf(p, v4.x, acc[4 * j + 0]);
                acc[4 * j + 1] = fmaf(p, v4.y, acc[4 * j + 1]);
                acc[4 * j + 2] = fmaf(p, v4.z, acc[4 * j + 2]);
                acc[4 * j + 3] = fmaf(p, v4.w, acc[4 * j + 3]);
            }
        }
    }

    float lt = l + __shfl_xor_sync(0xffffffffu, l, 1);
    lt = lt + __shfl_xor_sync(0xffffffffu, lt, 2);
    float inv = 1.f / lt;
    float* orow = g_attn + ((size_t)bh * S + (size_t)qt * BM + r) * DM + d0;
    #pragma unroll
    for (int j = 0; j < 8; j++) {
        ((float4*)orow)[j] = make_float4(acc[4 * j + 0] * inv, acc[4 * j + 1] * inv,
                                         acc[4 * j + 2] * inv, acc[4 * j + 3] * inv);
    }
}

// ------------------------------------------------------------------
// Kernel 3: output projection  A[8192,1024] (head-gathered) @ Wo + bo
// ------------------------------------------------------------------
__global__ __launch_bounds__(256) void oproj_kernel(
    const float* __restrict__ Wo, const float* __restrict__ bo,
    float* __restrict__ out)
{
    __shared__ float as[64 * 68];
    __shared__ float ws[64 * 68];   // ws[c][k]

    const int tid = threadIdx.x;
    const int gc0 = (int)blockIdx.x * 64;   // 0..1
    const int gr0 = (int)blockIdx.y * 64;   // 0..127
    const int r0 = (tid >> 4) << 2;
    const int c0 = (tid & 15) << 2;

    float acc[4][4];
    #pragma unroll
    for (int i = 0; i < 4; i++)
        #pragma unroll
        for (int j = 0; j < 4; j++) acc[i][j] = 0.f;

    for (int kc = 0; kc < DI; kc += 64) {
        int hh = kc >> 7;
        int dbase = kc & 127;
        #pragma unroll
        for (int i = 0; i < 4; i++) {
            int v = tid + i * 256;
            int row = v >> 4, k = (v & 15) << 2;
            int gr = gr0 + row;
            int bb = gr >> 11, ss = gr & 2047;
            *(float4*)&as[row * 68 + k] =
                *(const float4*)&g_attn[(((size_t)(bb * H + hh)) * S + ss) * DM + dbase + k];
        }
        #pragma unroll
        for (int i = 0; i < 4; i++) {
            int v = tid + i * 256;
            int k = v >> 4, c = (v & 15) << 2;
            float4 t = *(const float4*)&Wo[((size_t)(kc + k)) * DM + gc0 + c];
            ws[(c + 0) * 68 + k] = t.x;
            ws[(c + 1) * 68 + k] = t.y;
            ws[(c + 2) * 68 + k] = t.z;
            ws[(c + 3) * 68 + k] = t.w;
        }
        __syncthreads();
        #pragma unroll 4
        for (int kk = 0; kk < 64; kk += 4) {
            float4 a[4], b[4];
            #pragma unroll
            for (int i = 0; i < 4; i++) a[i] = *(const float4*)&as[(r0 + i) * 68 + kk];
            #pragma unroll
            for (int j = 0; j < 4; j++) b[j] = *(const float4*)&ws[(c0 + j) * 68 + kk];
            #pragma unroll
            for (int i = 0; i < 4; i++)
                #pragma unroll
                for (int j = 0; j < 4; j++)
                    acc[i][j] = fmaf(a[i].x, b[j].x, fmaf(a[i].y, b[j].y,
                                fmaf(a[i].z, b[j].z, fmaf(a[i].w, b[j].w, acc[i][j]))));
        }
        __syncthreads();
    }

    float bb0 = bo[gc0 + c0], bb1 = bo[gc0 + c0 + 1];
    float bb2 = bo[gc0 + c0 + 2], bb3 = bo[gc0 + c0 + 3];
    #pragma unroll
    for (int i = 0; i < 4; i++) {
        int gr = gr0 + r0 + i;
        *(float4*)&out[(size_t)gr * DM + gc0 + c0] =
            make_float4(acc[i][0] + bb0, acc[i][1] + bb1,
                        acc[i][2] + bb2, acc[i][3] + bb3);
    }
}

// ------------------------------------------------------------------
extern "C" void kernel_launch(void* const* d_in, const int* in_sizes, int n_in,
                              void* d_out, int out_size)
{
    const float* query = (const float*)d_in[0];
    const float* key   = (const float*)d_in[1];
    const float* value = (const float*)d_in[2];
    // d_in[3] = mask (tril, implemented analytically)
    const float* Wq = (const float*)d_in[4];
    const float* bq = (const float*)d_in[5];
    const float* Wk = (const float*)d_in[6];
    const float* bk = (const float*)d_in[7];
    const float* Wv = (const float*)d_in[8];
    const float* bv = (const float*)d_in[9];
    const float* Wo = (const float*)d_in[10];
    const float* bo = (const float*)d_in[11];
    float* out = (float*)d_out;

    const int qkv_smem = 2 * 64 * 132 * 4;
    cudaFuncSetAttribute(qkv_kernel, cudaFuncAttributeMaxDynamicSharedMemorySize, qkv_smem);
    cudaFuncSetAttribute(attn_kernel, cudaFuncAttributeMaxDynamicSharedMemorySize, ATTN_SMEM);

    qkv_kernel<<<dim3(16, 128, 3), 256, qkv_smem>>>(query, key, value,
                                                    Wq, bq, Wk, bk, Wv, bv);
    attn_kernel<<<dim3(16, 32), 512, ATTN_SMEM>>>();
    oproj_kernel<<<dim3(2, 128), 256>>>(Wo, bo, out);
}

// round 4
// speedup vs baseline: 10.6584x; 10.6584x over previous
#include <cuda_runtime.h>
#include <cuda_bf16.h>
#include <math.h>
#include <stdint.h>

#define B 4
#define S 2048
#define DM 128
#define H 8
#define DI 1024

// Global scratch (static __device__, no allocation). Plain row-major [bh][s][d].
__device__ __align__(16) __nv_bfloat16 g_qhi[B*H*S*DM];
__device__ __align__(16) __nv_bfloat16 g_qlo[B*H*S*DM];
__device__ __align__(16) __nv_bfloat16 g_khi[B*H*S*DM];
__device__ __align__(16) __nv_bfloat16 g_klo[B*H*S*DM];
__device__ __align__(16) __nv_bfloat16 g_vhi[B*H*S*DM];
__device__ __align__(16) __nv_bfloat16 g_vlo[B*H*S*DM];
__device__ __align__(16) float g_attn[B*H*S*DM];

// ------------------------------------------------------------------
// helpers
// ------------------------------------------------------------------
__device__ __forceinline__ uint32_t smem_u32(const void* p) {
    uint32_t a;
    asm("{ .reg .u64 t; cvta.to.shared.u64 t, %1; cvt.u32.u64 %0, t; }" : "=r"(a) : "l"(p));
    return a;
}
__device__ __forceinline__ void mma_bf16(float c[4], uint32_t a0, uint32_t a1,
                                         uint32_t a2, uint32_t a3,
                                         uint32_t b0, uint32_t b1) {
    asm volatile(
        "mma.sync.aligned.m16n8k16.row.col.f32.bf16.bf16.f32 "
        "{%0,%1,%2,%3}, {%4,%5,%6,%7}, {%8,%9}, {%0,%1,%2,%3};"
        : "+f"(c[0]), "+f"(c[1]), "+f"(c[2]), "+f"(c[3])
        : "r"(a0), "r"(a1), "r"(a2), "r"(a3), "r"(b0), "r"(b1));
}
__device__ __forceinline__ void ldsm4(uint32_t addr, uint32_t& r0, uint32_t& r1,
                                      uint32_t& r2, uint32_t& r3) {
    asm volatile("ldmatrix.sync.aligned.m8n8.x4.shared.b16 {%0,%1,%2,%3}, [%4];"
                 : "=r"(r0), "=r"(r1), "=r"(r2), "=r"(r3) : "r"(addr));
}
__device__ __forceinline__ void ldsm4t(uint32_t addr, uint32_t& r0, uint32_t& r1,
                                       uint32_t& r2, uint32_t& r3) {
    asm volatile("ldmatrix.sync.aligned.m8n8.x4.trans.shared.b16 {%0,%1,%2,%3}, [%4];"
                 : "=r"(r0), "=r"(r1), "=r"(r2), "=r"(r3) : "r"(addr));
}
__device__ __forceinline__ uint32_t packbf(float a, float b) {
    __nv_bfloat162 h = __floats2bfloat162_rn(a, b);
    return *(uint32_t*)&h;
}
// pack hi parts and residual-lo parts of (a,b)
__device__ __forceinline__ void packsplit(float a, float b, uint32_t& hi, uint32_t& lo) {
    __nv_bfloat162 h = __floats2bfloat162_rn(a, b);
    hi = *(uint32_t*)&h;
    __nv_bfloat162 l = __floats2bfloat162_rn(a - __low2float(h), b - __high2float(h));
    lo = *(uint32_t*)&l;
}
// split 4 floats -> bf16 hi/lo packed pairs
__device__ __forceinline__ void split4(float v0, float v1, float v2, float v3,
                                       uint2& h, uint2& lo) {
    __nv_bfloat162 h01 = __floats2bfloat162_rn(v0, v1);
    __nv_bfloat162 h23 = __floats2bfloat162_rn(v2, v3);
    __nv_bfloat162 l01 = __floats2bfloat162_rn(v0 - __low2float(h01), v1 - __high2float(h01));
    __nv_bfloat162 l23 = __floats2bfloat162_rn(v2 - __low2float(h23), v3 - __high2float(h23));
    h  = make_uint2(*(uint32_t*)&h01, *(uint32_t*)&h23);
    lo = make_uint2(*(uint32_t*)&l01, *(uint32_t*)&l23);
}

// Accurate sincos (double-assisted range reduction; fast-math immune)
__device__ __forceinline__ void sincos_acc(float x, float* so, float* co) {
    double td = (double)x;
    int qi = __double2int_rn(td * 0.63661977236758138);
    float r = (float)(td - (double)qi * 1.5707963267948966);
    float r2 = r * r;
    float sp = fmaf(r2, -1.9840874e-4f, 8.3333310e-3f);
    sp = fmaf(r2, sp, -1.6666667e-1f);
    sp = fmaf(r * r2, sp, r);
    float cp = fmaf(r2, 2.4760495e-5f, -1.3888397e-3f);
    cp = fmaf(r2, cp, 4.16666418e-2f);
    cp = fmaf(r2, cp, -0.5f);
    cp = fmaf(r2, cp, 1.0f);
    int n = qi & 3;
    float s = sp, c = cp;
    if (n & 1) { float t = s; s = c; c = -t; }
    if (n & 2) { s = -s; c = -c; }
    *so = s; *co = c;
}

// ------------------------------------------------------------------
// Kernel 1: QKV projection + bias (+RoPE, and 1/sqrt(128) pre-scale for Q),
// outputs bf16 hi/lo row-major.
// ------------------------------------------------------------------
__global__ __launch_bounds__(256) void qkv_kernel(
    const float* __restrict__ xq, const float* __restrict__ xk, const float* __restrict__ xv,
    const float* __restrict__ Wq, const float* __restrict__ bq,
    const float* __restrict__ Wk, const float* __restrict__ bk,
    const float* __restrict__ Wv, const float* __restrict__ bv)
{
    const int which = blockIdx.z;
    const float* X    = (which == 0) ? xq : (which == 1) ? xk : xv;
    const float* W    = (which == 0) ? Wq : (which == 1) ? Wk : Wv;
    const float* bias = (which == 0) ? bq : (which == 1) ? bk : bv;
    __nv_bfloat16* OHI = (which == 0) ? g_qhi : (which == 1) ? g_khi : g_vhi;
    __nv_bfloat16* OLO = (which == 0) ? g_qlo : (which == 1) ? g_klo : g_vlo;

    extern __shared__ float sm[];
    float* xs = sm;              // [64][132]
    float* ws = sm + 64 * 132;   // [64][132] transposed

    const int tid = threadIdx.x;
    const int gr0 = (int)blockIdx.y * 64;
    const int gc0 = (int)blockIdx.x * 64;

    #pragma unroll
    for (int i = 0; i < 8; i++) {
        int v = tid + i * 256;
        int row = v >> 5, c4 = (v & 31) << 2;
        *(float4*)&xs[row * 132 + c4] = *(const float4*)&X[(size_t)(gr0 + row) * DM + c4];
    }
    #pragma unroll
    for (int i = 0; i < 8; i++) {
        int v = tid + i * 256;
        int k = v >> 4, c = (v & 15) << 2;
        float4 t = *(const float4*)&W[(size_t)k * DI + gc0 + c];
        ws[(c + 0) * 132 + k] = t.x;
        ws[(c + 1) * 132 + k] = t.y;
        ws[(c + 2) * 132 + k] = t.z;
        ws[(c + 3) * 132 + k] = t.w;
    }
    __syncthreads();

    const int r0 = (tid >> 4) << 2;
    const int c0 = (tid & 15) << 2;

    float acc[4][4];
    #pragma unroll
    for (int i = 0; i < 4; i++)
        #pragma unroll
        for (int j = 0; j < 4; j++) acc[i][j] = 0.f;

    #pragma unroll 8
    for (int kk = 0; kk < 128; kk += 4) {
        float4 a[4], b[4];
        #pragma unroll
        for (int i = 0; i < 4; i++) a[i] = *(const float4*)&xs[(r0 + i) * 132 + kk];
        #pragma unroll
        for (int j = 0; j < 4; j++) b[j] = *(const float4*)&ws[(c0 + j) * 132 + kk];
        #pragma unroll
        for (int i = 0; i < 4; i++)
            #pragma unroll
            for (int j = 0; j < 4; j++)
                acc[i][j] = fmaf(a[i].x, b[j].x, fmaf(a[i].y, b[j].y,
                            fmaf(a[i].z, b[j].z, fmaf(a[i].w, b[j].w, acc[i][j]))));
    }

    const int gc = gc0 + c0;
    const int hh = gc >> 7;
    const int d0 = gc & 127;
    float b0 = bias[gc], b1 = bias[gc + 1], b2 = bias[gc + 2], b3 = bias[gc + 3];

    float invf0 = 0.f, invf1 = 0.f;
    if (which < 2) {
        const double c13 = 13.287712379549449 / 128.0;
        invf0 = (float)exp2(-(double)(d0)     * c13);
        invf1 = (float)exp2(-(double)(d0 + 2) * c13);
    }
    const float QSCL = 0.08838834764831845f;   // 1/sqrt(128), folded into Q

    #pragma unroll
    for (int i = 0; i < 4; i++) {
        int gr = gr0 + r0 + i;
        int bb = gr >> 11;
        int ss = gr & 2047;
        int bhh = bb * H + hh;
        float v0 = acc[i][0] + b0;
        float v1 = acc[i][1] + b1;
        float v2 = acc[i][2] + b2;
        float v3 = acc[i][3] + b3;
        if (which < 2) {
            float th0 = (float)ss * invf0;
            float th1 = (float)ss * invf1;
            float s0, cc0, s1, cc1;
            sincos_acc(th0, &s0, &cc0);
            sincos_acc(th1, &s1, &cc1);
            float o0 = v0 * cc0 - v1 * s0;
            float o1 = v1 * cc0 + v0 * s0;
            float o2 = v2 * cc1 - v3 * s1;
            float o3 = v3 * cc1 + v2 * s1;
            v0 = o0; v1 = o1; v2 = o2; v3 = o3;
            if (which == 0) { v0 *= QSCL; v1 *= QSCL; v2 *= QSCL; v3 *= QSCL; }
        }
        uint2 hi2, lo2;
        split4(v0, v1, v2, v3, hi2, lo2);
        size_t off = ((size_t)bhh * S + ss) * DM + d0;
        *reinterpret_cast<uint2*>(reinterpret_cast<char*>(OHI) + off * 2) = hi2;
        *reinterpret_cast<uint2*>(reinterpret_cast<char*>(OLO) + off * 2) = lo2;
    }
}

// ------------------------------------------------------------------
// Kernel 2: causal flash attention with mma.sync (HMMA bf16, hi/lo split).
// CTA = 256 thr / 8 warps; warp w owns q-rows [16w,16w+16) of a 128-row tile.
// K/V tiles (BN=64 keys) staged in smem; Q frags in registers.
// No-max softmax; O accumulated unnormalized in fp32 frags.
// ------------------------------------------------------------------
#define KVSTRIDE 272           // 136 bf16 per row (128 + 8 pad)
#define OFF_KH 0
#define OFF_KL (64 * KVSTRIDE)
#define OFF_VH (2 * 64 * KVSTRIDE)
#define OFF_VL (3 * 64 * KVSTRIDE)
#define ATTN_SMEM (4 * 64 * KVSTRIDE)

__global__ __launch_bounds__(256, 1) void attn_kernel()
{
    extern __shared__ char smem[];
    const uint32_t sb = smem_u32(smem);
    const int tid  = threadIdx.x;
    const int w    = tid >> 5;
    const int lane = tid & 31;
    const int bh   = blockIdx.y;
    const int qt   = 15 - (int)blockIdx.x;

    const int g  = lane >> 2;       // 0..7  (row within 8)
    const int cq = lane & 3;        // 0..3  (col pair)

    // ---- load Q fragments (hi/lo) straight from gmem ----
    uint32_t qh[8][4], ql[8][4];
    {
        const uint32_t* Qh32 = (const uint32_t*)g_qhi;
        const uint32_t* Ql32 = (const uint32_t*)g_qlo;
        size_t rowA = (size_t)bh * S + qt * 128 + 16 * w + g;
        size_t rowB = rowA + 8;
        #pragma unroll
        for (int j = 0; j < 8; j++) {
            int cA = (cq << 1) + 16 * j;            // even col
            size_t iA = rowA * 64 + (cA >> 1);
            size_t iB = rowB * 64 + (cA >> 1);
            qh[j][0] = Qh32[iA];     qh[j][1] = Qh32[iB];
            qh[j][2] = Qh32[iA + 4]; qh[j][3] = Qh32[iB + 4];
            ql[j][0] = Ql32[iA];     ql[j][1] = Ql32[iB];
            ql[j][2] = Ql32[iA + 4]; ql[j][3] = Ql32[iB + 4];
        }
    }

    // ldmatrix lane offsets
    const uint32_t loffK = (uint32_t)((lane & 7) * KVSTRIDE + (lane >> 3) * 16);
    const uint32_t loffV = (uint32_t)((lane & 7) * KVSTRIDE + ((lane >> 3) & 1) * 8 * KVSTRIDE
                                      + (lane >> 4) * 16);

    float o[16][4];
    #pragma unroll
    for (int n = 0; n < 16; n++)
        #pragma unroll
        for (int i = 0; i < 4; i++) o[n][i] = 0.f;
    float l_a = 0.f, l_b = 0.f;

    const int rowAg = qt * 128 + 16 * w + g;      // global q row (thread's row A)
    const int nkt = 2 * qt + 2;

    for (int kt = 0; kt < nkt; kt++) {
        if (kt) __syncthreads();
        // ---- stage K/V hi/lo tile (64 x 128 bf16 each) ----
        {
            size_t srcbase = ((size_t)bh * S + (size_t)kt * 64) * DM / 8;  // uint4 units
            const uint4* kh4 = (const uint4*)g_khi + srcbase;
            const uint4* kl4 = (const uint4*)g_klo + srcbase;
            const uint4* vh4 = (const uint4*)g_vhi + srcbase;
            const uint4* vl4 = (const uint4*)g_vlo + srcbase;
            #pragma unroll
            for (int i = 0; i < 4; i++) {
                int x = tid + i * 256;          // 0..1023
                int row = x >> 4, c = x & 15;
                uint32_t doff = (uint32_t)(row * KVSTRIDE + c * 16);
                int sidx = row * 16 + c;
                *(uint4*)(smem + OFF_KH + doff) = kh4[sidx];
                *(uint4*)(smem + OFF_KL + doff) = kl4[sidx];
                *(uint4*)(smem + OFF_VH + doff) = vh4[sidx];
                *(uint4*)(smem + OFF_VL + doff) = vl4[sidx];
            }
        }
        __syncthreads();

        // ---- S = Q K^T (3-product hi/lo) ----
        float sfrag[8][4];
        #pragma unroll
        for (int nt = 0; nt < 8; nt++) {
            float* c = sfrag[nt];
            c[0] = c[1] = c[2] = c[3] = 0.f;
            uint32_t baseH = sb + OFF_KH + (uint32_t)(nt * 8 * KVSTRIDE) + loffK;
            uint32_t baseL = sb + OFF_KL + (uint32_t)(nt * 8 * KVSTRIDE) + loffK;
            #pragma unroll
            for (int kk = 0; kk < 4; kk++) {
                uint32_t h0, h1, h2, h3, e0, e1, e2, e3;
                ldsm4(baseH + (uint32_t)(kk * 64), h0, h1, h2, h3);
                ldsm4(baseL + (uint32_t)(kk * 64), e0, e1, e2, e3);
                int j = 2 * kk;
                mma_bf16(c, qh[j][0], qh[j][1], qh[j][2], qh[j][3], h0, h1);
                mma_bf16(c, qh[j+1][0], qh[j+1][1], qh[j+1][2], qh[j+1][3], h2, h3);
                mma_bf16(c, ql[j][0], ql[j][1], ql[j][2], ql[j][3], h0, h1);
                mma_bf16(c, ql[j+1][0], ql[j+1][1], ql[j+1][2], ql[j+1][3], h2, h3);
                mma_bf16(c, qh[j][0], qh[j][1], qh[j][2], qh[j][3], e0, e1);
                mma_bf16(c, qh[j+1][0], qh[j+1][1], qh[j+1][2], qh[j+1][3], e2, e3);
            }
        }

        // ---- softmax (no max-sub; scores pre-scaled) + causal mask ----
        const bool diag = (kt >= 2 * qt);
        const int colb = kt * 64 + 2 * cq;
        float lsa = 0.f, lsb = 0.f;
        #pragma unroll
        for (int nt = 0; nt < 8; nt++) {
            float* c = sfrag[nt];
            float p0 = __expf(c[0]);
            float p1 = __expf(c[1]);
            float p2 = __expf(c[2]);
            float p3 = __expf(c[3]);
            if (diag) {
                int cc = colb + 8 * nt;
                if (cc     > rowAg)     p0 = 0.f;
                if (cc + 1 > rowAg)     p1 = 0.f;
                if (cc     > rowAg + 8) p2 = 0.f;
                if (cc + 1 > rowAg + 8) p3 = 0.f;
            }
            c[0] = p0; c[1] = p1; c[2] = p2; c[3] = p3;
            lsa += p0 + p1;
            lsb += p2 + p3;
        }
        l_a += lsa;
        l_b += lsb;

        // ---- P fragments (hi/lo) from S frags, register-to-register ----
        uint32_t ah[4][4], al[4][4];
        #pragma unroll
        for (int ks = 0; ks < 4; ks++) {
            packsplit(sfrag[2*ks][0],   sfrag[2*ks][1],   ah[ks][0], al[ks][0]);
            packsplit(sfrag[2*ks][2],   sfrag[2*ks][3],   ah[ks][1], al[ks][1]);
            packsplit(sfrag[2*ks+1][0], sfrag[2*ks+1][1], ah[ks][2], al[ks][2]);
            packsplit(sfrag[2*ks+1][2], sfrag[2*ks+1][3], ah[ks][3], al[ks][3]);
        }

        // ---- O += P V (3-product hi/lo) ----
        #pragma unroll
        for (int np = 0; np < 8; np++) {
            uint32_t baseH = sb + OFF_VH + (uint32_t)(np * 32) + loffV;
            uint32_t baseL = sb + OFF_VL + (uint32_t)(np * 32) + loffV;
            float* oa = o[2 * np];
            float* ob = o[2 * np + 1];
            #pragma unroll
            for (int ks = 0; ks < 4; ks++) {
                uint32_t h0, h1, h2, h3, e0, e1, e2, e3;
                ldsm4t(baseH + (uint32_t)(ks * 16 * KVSTRIDE), h0, h1, h2, h3);
                ldsm4t(baseL + (uint32_t)(ks * 16 * KVSTRIDE), e0, e1, e2, e3);
                mma_bf16(oa, ah[ks][0], ah[ks][1], ah[ks][2], ah[ks][3], h0, h1);
                mma_bf16(ob, ah[ks][0], ah[ks][1], ah[ks][2], ah[ks][3], h2, h3);
                mma_bf16(oa, al[ks][0], al[ks][1], al[ks][2], al[ks][3], h0, h1);
                mma_bf16(ob, al[ks][0], al[ks][1], al[ks][2], al[ks][3], h2, h3);
                mma_bf16(oa, ah[ks][0], ah[ks][1], ah[ks][2], ah[ks][3], e0, e1);
                mma_bf16(ob, ah[ks][0], ah[ks][1], ah[ks][2], ah[ks][3], e2, e3);
            }
        }
    }

    // ---- row sums across quad, normalize, store ----
    l_a += __shfl_xor_sync(0xffffffffu, l_a, 1);
    l_a += __shfl_xor_sync(0xffffffffu, l_a, 2);
    l_b += __shfl_xor_sync(0xffffffffu, l_b, 1);
    l_b += __shfl_xor_sync(0xffffffffu, l_b, 2);
    float inva = 1.f / l_a;
    float invb = 1.f / l_b;

    {
        size_t rowA = (size_t)bh * S + qt * 128 + 16 * w + g;
        float* pa = g_attn + rowA * DM + 2 * cq;
        float* pb = pa + 8 * DM;
        #pragma unroll
        for (int n = 0; n < 16; n++) {
            *(float2*)(pa + 8 * n) = make_float2(o[n][0] * inva, o[n][1] * inva);
            *(float2*)(pb + 8 * n) = make_float2(o[n][2] * invb, o[n][3] * invb);
        }
    }
}

// ------------------------------------------------------------------
// Kernel 3: output projection  A[8192,1024] (head-gathered) @ Wo + bo
// ------------------------------------------------------------------
__global__ __launch_bounds__(256) void oproj_kernel(
    const float* __restrict__ Wo, const float* __restrict__ bo,
    float* __restrict__ out)
{
    __shared__ float as[64 * 68];
    __shared__ float ws[64 * 68];

    const int tid = threadIdx.x;
    const int gc0 = (int)blockIdx.x * 64;
    const int gr0 = (int)blockIdx.y * 64;
    const int r0 = (tid >> 4) << 2;
    const int c0 = (tid & 15) << 2;

    float acc[4][4];
    #pragma unroll
    for (int i = 0; i < 4; i++)
        #pragma unroll
        for (int j = 0; j < 4; j++) acc[i][j] = 0.f;

    for (int kc = 0; kc < DI; kc += 64) {
        int hh = kc >> 7;
        int dbase = kc & 127;
        #pragma unroll
        for (int i = 0; i < 4; i++) {
            int v = tid + i * 256;
            int row = v >> 4, k = (v & 15) << 2;
            int gr = gr0 + row;
            int bb = gr >> 11, ss = gr & 2047;
            *(float4*)&as[row * 68 + k] =
                *(const float4*)&g_attn[(((size_t)(bb * H + hh)) * S + ss) * DM + dbase + k];
        }
        #pragma unroll
        for (int i = 0; i < 4; i++) {
            int v = tid + i * 256;
            int k = v >> 4, c = (v & 15) << 2;
            float4 t = *(const float4*)&Wo[((size_t)(kc + k)) * DM + gc0 + c];
            ws[(c + 0) * 68 + k] = t.x;
            ws[(c + 1) * 68 + k] = t.y;
            ws[(c + 2) * 68 + k] = t.z;
            ws[(c + 3) * 68 + k] = t.w;
        }
        __syncthreads();
        #pragma unroll 4
        for (int kk = 0; kk < 64; kk += 4) {
            float4 a[4], b[4];
            #pragma unroll
            for (int i = 0; i < 4; i++) a[i] = *(const float4*)&as[(r0 + i) * 68 + kk];
            #pragma unroll
            for (int j = 0; j < 4; j++) b[j] = *(const float4*)&ws[(c0 + j) * 68 + kk];
            #pragma unroll
            for (int i = 0; i < 4; i++)
                #pragma unroll
                for (int j = 0; j < 4; j++)
                    acc[i][j] = fmaf(a[i].x, b[j].x, fmaf(a[i].y, b[j].y,
                                fmaf(a[i].z, b[j].z, fmaf(a[i].w, b[j].w, acc[i][j]))));
        }
        __syncthreads();
    }

    float bb0 = bo[gc0 + c0], bb1 = bo[gc0 + c0 + 1];
    float bb2 = bo[gc0 + c0 + 2], bb3 = bo[gc0 + c0 + 3];
    #pragma unroll
    for (int i = 0; i < 4; i++) {
        int gr = gr0 + r0 + i;
        *(float4*)&out[(size_t)gr * DM + gc0 + c0] =
            make_float4(acc[i][0] + bb0, acc[i][1] + bb1,
                        acc[i][2] + bb2, acc[i][3] + bb3);
    }
}

// ------------------------------------------------------------------
extern "C" void kernel_launch(void* const* d_in, const int* in_sizes, int n_in,
                              void* d_out, int out_size)
{
    const float* query = (const float*)d_in[0];
    const float* key   = (const float*)d_in[1];
    const float* value = (const float*)d_in[2];
    // d_in[3] = mask (tril, implemented analytically)
    const float* Wq = (const float*)d_in[4];
    const float* bq = (const float*)d_in[5];
    const float* Wk = (const float*)d_in[6];
    const float* bk = (const float*)d_in[7];
    const float* Wv = (const float*)d_in[8];
    const float* bv = (const float*)d_in[9];
    const float* Wo = (const float*)d_in[10];
    const float* bo = (const float*)d_in[11];
    float* out = (float*)d_out;

    const int qkv_smem = 2 * 64 * 132 * 4;
    cudaFuncSetAttribute(qkv_kernel, cudaFuncAttributeMaxDynamicSharedMemorySize, qkv_smem);
    cudaFuncSetAttribute(attn_kernel, cudaFuncAttributeMaxDynamicSharedMemorySize, ATTN_SMEM);

    qkv_kernel<<<dim3(16, 128, 3), 256, qkv_smem>>>(query, key, value,
                                                    Wq, bq, Wk, bk, Wv, bv);
    attn_kernel<<<dim3(16, 32), 256, ATTN_SMEM>>>();
    oproj_kernel<<<dim3(2, 128), 256>>>(Wo, bo, out);
}

// round 5
// speedup vs baseline: 19.9629x; 1.8730x over previous
#include <cuda_runtime.h>
#include <cuda_bf16.h>
#include <math.h>
#include <stdint.h>

#define B 4
#define SEQ 2048
#define DM 128
#define H 8
#define DI 1024

// Global scratch (static __device__, no allocation). Row-major [bh][s][d].
__device__ __align__(16) __nv_bfloat16 g_qhi[B*H*SEQ*DM];
__device__ __align__(16) __nv_bfloat16 g_qlo[B*H*SEQ*DM];
__device__ __align__(16) __nv_bfloat16 g_khi[B*H*SEQ*DM];
__device__ __align__(16) __nv_bfloat16 g_klo[B*H*SEQ*DM];
__device__ __align__(16) __nv_bfloat16 g_vhi[B*H*SEQ*DM];
__device__ __align__(16) __nv_bfloat16 g_vlo[B*H*SEQ*DM];
__device__ __align__(16) __nv_bfloat16 g_ohi[B*H*SEQ*DM];
__device__ __align__(16) __nv_bfloat16 g_olo[B*H*SEQ*DM];
__device__ __align__(8)  float2 g_rope[SEQ*64];   // (cos, sin) per (pos, dpair)

// ------------------------------------------------------------------
// helpers
// ------------------------------------------------------------------
__device__ __forceinline__ uint32_t smem_u32(const void* p) {
    uint32_t a;
    asm("{ .reg .u64 t; cvta.to.shared.u64 t, %1; cvt.u32.u64 %0, t; }" : "=r"(a) : "l"(p));
    return a;
}
__device__ __forceinline__ void mma_bf16(float c[4], uint32_t a0, uint32_t a1,
                                         uint32_t a2, uint32_t a3,
                                         uint32_t b0, uint32_t b1) {
    asm volatile(
        "mma.sync.aligned.m16n8k16.row.col.f32.bf16.bf16.f32 "
        "{%0,%1,%2,%3}, {%4,%5,%6,%7}, {%8,%9}, {%0,%1,%2,%3};"
        : "+f"(c[0]), "+f"(c[1]), "+f"(c[2]), "+f"(c[3])
        : "r"(a0), "r"(a1), "r"(a2), "r"(a3), "r"(b0), "r"(b1));
}
__device__ __forceinline__ void ldsm4(uint32_t addr, uint32_t& r0, uint32_t& r1,
                                      uint32_t& r2, uint32_t& r3) {
    asm volatile("ldmatrix.sync.aligned.m8n8.x4.shared.b16 {%0,%1,%2,%3}, [%4];"
                 : "=r"(r0), "=r"(r1), "=r"(r2), "=r"(r3) : "r"(addr));
}
__device__ __forceinline__ void ldsm4t(uint32_t addr, uint32_t& r0, uint32_t& r1,
                                       uint32_t& r2, uint32_t& r3) {
    asm volatile("ldmatrix.sync.aligned.m8n8.x4.trans.shared.b16 {%0,%1,%2,%3}, [%4];"
                 : "=r"(r0), "=r"(r1), "=r"(r2), "=r"(r3) : "r"(addr));
}
__device__ __forceinline__ void packsplit(float a, float b, uint32_t& hi, uint32_t& lo) {
    __nv_bfloat162 h = __floats2bfloat162_rn(a, b);
    hi = *(uint32_t*)&h;
    __nv_bfloat162 l = __floats2bfloat162_rn(a - __low2float(h), b - __high2float(h));
    lo = *(uint32_t*)&l;
}
__device__ __forceinline__ void split4(float v0, float v1, float v2, float v3,
                                       uint2& h, uint2& lo) {
    __nv_bfloat162 h01 = __floats2bfloat162_rn(v0, v1);
    __nv_bfloat162 h23 = __floats2bfloat162_rn(v2, v3);
    __nv_bfloat162 l01 = __floats2bfloat162_rn(v0 - __low2float(h01), v1 - __high2float(h01));
    __nv_bfloat162 l23 = __floats2bfloat162_rn(v2 - __low2float(h23), v3 - __high2float(h23));
    h  = make_uint2(*(uint32_t*)&h01, *(uint32_t*)&h23);
    lo = make_uint2(*(uint32_t*)&l01, *(uint32_t*)&l23);
}

// Accurate sincos (double-assisted range reduction; fast-math immune)
__device__ __forceinline__ void sincos_acc(float x, float* so, float* co) {
    double td = (double)x;
    int qi = __double2int_rn(td * 0.63661977236758138);
    float r = (float)(td - (double)qi * 1.5707963267948966);
    float r2 = r * r;
    float sp = fmaf(r2, -1.9840874e-4f, 8.3333310e-3f);
    sp = fmaf(r2, sp, -1.6666667e-1f);
    sp = fmaf(r * r2, sp, r);
    float cp = fmaf(r2, 2.4760495e-5f, -1.3888397e-3f);
    cp = fmaf(r2, cp, 4.16666418e-2f);
    cp = fmaf(r2, cp, -0.5f);
    cp = fmaf(r2, cp, 1.0f);
    int n = qi & 3;
    float s = sp, c = cp;
    if (n & 1) { float t = s; s = c; c = -t; }
    if (n & 2) { s = -s; c = -c; }
    *so = s; *co = c;
}

// ------------------------------------------------------------------
// Kernel 0: RoPE table  (cos,sin)[pos][dpair]
// ------------------------------------------------------------------
__global__ __launch_bounds__(256) void rope_table_kernel()
{
    int idx = blockIdx.x * 256 + threadIdx.x;   // 0..131071
    int ss = idx >> 6, dp = idx & 63;
    const double c13 = 13.287712379549449 / 128.0;  // log2(10000)/128
    float invf = (float)exp2(-(double)(2 * dp) * c13);
    float th = (float)ss * invf;
    float s, c;
    sincos_acc(th, &s, &c);
    g_rope[idx] = make_float2(c, s);
}

// ------------------------------------------------------------------
// Kernel 1: QKV projection with HMMA (hi/lo split), epilogue does
// bias + RoPE (+Q pre-scale), writes bf16 hi/lo row-major.
// CTA: 128 rows x 128 cols (one head's d-block). grid (8, 64, 3).
// ------------------------------------------------------------------
#define PST 272                          // 128 bf16 + 8 pad, bytes
#define PJ_XHI 0
#define PJ_XLO 34816
#define PJ_WHI 69632
#define PJ_WLO 104448
#define PROJ_SMEM 139264

__global__ __launch_bounds__(256, 1) void proj_kernel(
    const float* __restrict__ xq, const float* __restrict__ xk, const float* __restrict__ xv,
    const float* __restrict__ Wq, const float* __restrict__ bq,
    const float* __restrict__ Wk, const float* __restrict__ bk,
    const float* __restrict__ Wv, const float* __restrict__ bv)
{
    extern __shared__ char smem[];
    const uint32_t sb = smem_u32(smem);
    const int which = blockIdx.z;
    const float* X    = (which == 0) ? xq : (which == 1) ? xk : xv;
    const float* W    = (which == 0) ? Wq : (which == 1) ? Wk : Wv;
    const float* bias = (which == 0) ? bq : (which == 1) ? bk : bv;
    uint32_t* OH = (uint32_t*)((which == 0) ? g_qhi : (which == 1) ? g_khi : g_vhi);
    uint32_t* OL = (uint32_t*)((which == 0) ? g_qlo : (which == 1) ? g_klo : g_vlo);

    const int tid = threadIdx.x;
    const int hh  = blockIdx.x;             // head = col tile
    const int gc0 = hh * 128;
    const int gr0 = (int)blockIdx.y * 128;

    // ---- stage X tile (fp32 -> bf16 hi/lo) ----
    #pragma unroll
    for (int i = 0; i < 16; i++) {
        int idx = tid + i * 256;
        int row = idx >> 5, c4 = (idx & 31) << 2;
        float4 t = *(const float4*)&X[(size_t)(gr0 + row) * DM + c4];
        uint2 h2, l2;
        split4(t.x, t.y, t.z, t.w, h2, l2);
        *(uint2*)(smem + PJ_XHI + row * PST + c4 * 2) = h2;
        *(uint2*)(smem + PJ_XLO + row * PST + c4 * 2) = l2;
    }
    // ---- stage W tile [k=128][n=128] (row-major k; trans at ldmatrix) ----
    #pragma unroll
    for (int i = 0; i < 16; i++) {
        int idx = tid + i * 256;
        int k = idx >> 5, ng = (idx & 31) << 2;
        float4 t = *(const float4*)&W[(size_t)k * DI + gc0 + ng];
        uint2 h2, l2;
        split4(t.x, t.y, t.z, t.w, h2, l2);
        *(uint2*)(smem + PJ_WHI + k * PST + ng * 2) = h2;
        *(uint2*)(smem + PJ_WLO + k * PST + ng * 2) = l2;
    }
    __syncthreads();

    const int w    = tid >> 5;
    const int lane = tid & 31;
    const int g    = lane >> 2;
    const int cq   = lane & 3;

    const uint32_t loffA = (uint32_t)((16 * w + (lane & 15)) * PST + (lane >> 4) * 16);
    const uint32_t loffB = (uint32_t)((lane & 7) * PST + ((lane >> 3) & 1) * 8 * PST
                                      + (lane >> 4) * 16);

    float c[16][4];
    #pragma unroll
    for (int n = 0; n < 16; n++) { c[n][0] = c[n][1] = c[n][2] = c[n][3] = 0.f; }

    #pragma unroll
    for (int ks = 0; ks < 8; ks++) {
        uint32_t ah0, ah1, ah2, ah3, al0, al1, al2, al3;
        ldsm4(sb + PJ_XHI + loffA + (uint32_t)(ks * 32), ah0, ah1, ah2, ah3);
        ldsm4(sb + PJ_XLO + loffA + (uint32_t)(ks * 32), al0, al1, al2, al3);
        #pragma unroll
        for (int np = 0; np < 8; np++) {
            uint32_t b0, b1, b2, b3, e0, e1, e2, e3;
            uint32_t off = loffB + (uint32_t)(np * 32 + ks * 16 * PST);
            ldsm4t(sb + PJ_WHI + off, b0, b1, b2, b3);
            ldsm4t(sb + PJ_WLO + off, e0, e1, e2, e3);
            float* ca = c[2 * np];
            float* cb = c[2 * np + 1];
            mma_bf16(ca, ah0, ah1, ah2, ah3, b0, b1);
            mma_bf16(ca, al0, al1, al2, al3, b0, b1);
            mma_bf16(ca, ah0, ah1, ah2, ah3, e0, e1);
            mma_bf16(cb, ah0, ah1, ah2, ah3, b2, b3);
            mma_bf16(cb, al0, al1, al2, al3, b2, b3);
            mma_bf16(cb, ah0, ah1, ah2, ah3, e2, e3);
        }
    }

    // ---- epilogue: bias + RoPE (+Q scale), split, store ----
    const int gr = gr0 + 16 * w + g;
    const int bb = gr >> 11, ss = gr & 2047;
    const size_t row1 = (size_t)(bb * H + hh) * SEQ + ss;
    const float QSCL = 0.08838834764831845f;

    #pragma unroll
    for (int nt = 0; nt < 16; nt++) {
        int d = nt * 8 + 2 * cq;
        float2 bi = *(const float2*)&bias[gc0 + d];
        float v0 = c[nt][0] + bi.x, v1 = c[nt][1] + bi.y;
        float v2 = c[nt][2] + bi.x, v3 = c[nt][3] + bi.y;
        if (which < 2) {
            int dp = nt * 4 + cq;
            float2 t1 = g_rope[ss * 64 + dp];
            float2 t2 = g_rope[(ss + 8) * 64 + dp];
            float o0 = v0 * t1.x - v1 * t1.y;
            float o1 = v1 * t1.x + v0 * t1.y;
            float o2 = v2 * t2.x - v3 * t2.y;
            float o3 = v3 * t2.x + v2 * t2.y;
            v0 = o0; v1 = o1; v2 = o2; v3 = o3;
            if (which == 0) { v0 *= QSCL; v1 *= QSCL; v2 *= QSCL; v3 *= QSCL; }
        }
        uint32_t h, lo;
        int dp = nt * 4 + cq;
        packsplit(v0, v1, h, lo);
        OH[row1 * 64 + dp] = h;
        OL[row1 * 64 + dp] = lo;
        packsplit(v2, v3, h, lo);
        OH[(row1 + 8) * 64 + dp] = h;
        OL[(row1 + 8) * 64 + dp] = lo;
    }
}

// ------------------------------------------------------------------
// Kernel 2: causal flash attention with mma.sync (HMMA bf16, hi/lo split).
// (mainloop unchanged from R4; epilogue now emits bf16 hi/lo)
// ------------------------------------------------------------------
#define KVSTRIDE 272
#define OFF_KH 0
#define OFF_KL (64 * KVSTRIDE)
#define OFF_VH (2 * 64 * KVSTRIDE)
#define OFF_VL (3 * 64 * KVSTRIDE)
#define ATTN_SMEM (4 * 64 * KVSTRIDE)

__global__ __launch_bounds__(256, 1) void attn_kernel()
{
    extern __shared__ char smem[];
    const uint32_t sb = smem_u32(smem);
    const int tid  = threadIdx.x;
    const int w    = tid >> 5;
    const int lane = tid & 31;
    const int bh   = blockIdx.y;
    const int qt   = 15 - (int)blockIdx.x;

    const int g  = lane >> 2;
    const int cq = lane & 3;

    uint32_t qh[8][4], ql[8][4];
    {
        const uint32_t* Qh32 = (const uint32_t*)g_qhi;
        const uint32_t* Ql32 = (const uint32_t*)g_qlo;
        size_t rowA = (size_t)bh * SEQ + qt * 128 + 16 * w + g;
        size_t rowB = rowA + 8;
        #pragma unroll
        for (int j = 0; j < 8; j++) {
            int cA = (cq << 1) + 16 * j;
            size_t iA = rowA * 64 + (cA >> 1);
            size_t iB = rowB * 64 + (cA >> 1);
            qh[j][0] = Qh32[iA];     qh[j][1] = Qh32[iB];
            qh[j][2] = Qh32[iA + 4]; qh[j][3] = Qh32[iB + 4];
            ql[j][0] = Ql32[iA];     ql[j][1] = Ql32[iB];
            ql[j][2] = Ql32[iA + 4]; ql[j][3] = Ql32[iB + 4];
        }
    }

    const uint32_t loffK = (uint32_t)((lane & 7) * KVSTRIDE + (lane >> 3) * 16);
    const uint32_t loffV = (uint32_t)((lane & 7) * KVSTRIDE + ((lane >> 3) & 1) * 8 * KVSTRIDE
                                      + (lane >> 4) * 16);

    float o[16][4];
    #pragma unroll
    for (int n = 0; n < 16; n++)
        #pragma unroll
        for (int i = 0; i < 4; i++) o[n][i] = 0.f;
    float l_a = 0.f, l_b = 0.f;

    const int rowAg = qt * 128 + 16 * w + g;
    const int nkt = 2 * qt + 2;

    for (int kt = 0; kt < nkt; kt++) {
        if (kt) __syncthreads();
        {
            size_t srcbase = ((size_t)bh * SEQ + (size_t)kt * 64) * DM / 8;
            const uint4* kh4 = (const uint4*)g_khi + srcbase;
            const uint4* kl4 = (const uint4*)g_klo + srcbase;
            const uint4* vh4 = (const uint4*)g_vhi + srcbase;
            const uint4* vl4 = (const uint4*)g_vlo + srcbase;
            #pragma unroll
            for (int i = 0; i < 4; i++) {
                int x = tid + i * 256;
                int row = x >> 4, c = x & 15;
                uint32_t doff = (uint32_t)(row * KVSTRIDE + c * 16);
                int sidx = row * 16 + c;
                *(uint4*)(smem + OFF_KH + doff) = kh4[sidx];
                *(uint4*)(smem + OFF_KL + doff) = kl4[sidx];
                *(uint4*)(smem + OFF_VH + doff) = vh4[sidx];
                *(uint4*)(smem + OFF_VL + doff) = vl4[sidx];
            }
        }
        __syncthreads();

        float sfrag[8][4];
        #pragma unroll
        for (int nt = 0; nt < 8; nt++) {
            float* c = sfrag[nt];
            c[0] = c[1] = c[2] = c[3] = 0.f;
            uint32_t baseH = sb + OFF_KH + (uint32_t)(nt * 8 * KVSTRIDE) + loffK;
            uint32_t baseL = sb + OFF_KL + (uint32_t)(nt * 8 * KVSTRIDE) + loffK;
            #pragma unroll
            for (int kk = 0; kk < 4; kk++) {
                uint32_t h0, h1, h2, h3, e0, e1, e2, e3;
                ldsm4(baseH + (uint32_t)(kk * 64), h0, h1, h2, h3);
                ldsm4(baseL + (uint32_t)(kk * 64), e0, e1, e2, e3);
                int j = 2 * kk;
                mma_bf16(c, qh[j][0], qh[j][1], qh[j][2], qh[j][3], h0, h1);
                mma_bf16(c, qh[j+1][0], qh[j+1][1], qh[j+1][2], qh[j+1][3], h2, h3);
                mma_bf16(c, ql[j][0], ql[j][1], ql[j][2], ql[j][3], h0, h1);
                mma_bf16(c, ql[j+1][0], ql[j+1][1], ql[j+1][2], ql[j+1][3], h2, h3);
                mma_bf16(c, qh[j][0], qh[j][1], qh[j][2], qh[j][3], e0, e1);
                mma_bf16(c, qh[j+1][0], qh[j+1][1], qh[j+1][2], qh[j+1][3], e2, e3);
            }
        }

        const bool diag = (kt >= 2 * qt);
        const int colb = kt * 64 + 2 * cq;
        float lsa = 0.f, lsb = 0.f;
        #pragma unroll
        for (int nt = 0; nt < 8; nt++) {
            float* c = sfrag[nt];
            float p0 = __expf(c[0]);
            float p1 = __expf(c[1]);
            float p2 = __expf(c[2]);
            float p3 = __expf(c[3]);
            if (diag) {
                int cc = colb + 8 * nt;
                if (cc     > rowAg)     p0 = 0.f;
                if (cc + 1 > rowAg)     p1 = 0.f;
                if (cc     > rowAg + 8) p2 = 0.f;
                if (cc + 1 > rowAg + 8) p3 = 0.f;
            }
            c[0] = p0; c[1] = p1; c[2] = p2; c[3] = p3;
            lsa += p0 + p1;
            lsb += p2 + p3;
        }
        l_a += lsa;
        l_b += lsb;

        uint32_t ah[4][4], al[4][4];
        #pragma unroll
        for (int ks = 0; ks < 4; ks++) {
            packsplit(sfrag[2*ks][0],   sfrag[2*ks][1],   ah[ks][0], al[ks][0]);
            packsplit(sfrag[2*ks][2],   sfrag[2*ks][3],   ah[ks][1], al[ks][1]);
            packsplit(sfrag[2*ks+1][0], sfrag[2*ks+1][1], ah[ks][2], al[ks][2]);
            packsplit(sfrag[2*ks+1][2], sfrag[2*ks+1][3], ah[ks][3], al[ks][3]);
        }

        #pragma unroll
        for (int np = 0; np < 8; np++) {
            uint32_t baseH = sb + OFF_VH + (uint32_t)(np * 32) + loffV;
            uint32_t baseL = sb + OFF_VL + (uint32_t)(np * 32) + loffV;
            float* oa = o[2 * np];
            float* ob = o[2 * np + 1];
            #pragma unroll
            for (int ks = 0; ks < 4; ks++) {
                uint32_t h0, h1, h2, h3, e0, e1, e2, e3;
                ldsm4t(baseH + (uint32_t)(ks * 16 * KVSTRIDE), h0, h1, h2, h3);
                ldsm4t(baseL + (uint32_t)(ks * 16 * KVSTRIDE), e0, e1, e2, e3);
                mma_bf16(oa, ah[ks][0], ah[ks][1], ah[ks][2], ah[ks][3], h0, h1);
                mma_bf16(ob, ah[ks][0], ah[ks][1], ah[ks][2], ah[ks][3], h2, h3);
                mma_bf16(oa, al[ks][0], al[ks][1], al[ks][2], al[ks][3], h0, h1);
                mma_bf16(ob, al[ks][0], al[ks][1], al[ks][2], al[ks][3], h2, h3);
                mma_bf16(oa, ah[ks][0], ah[ks][1], ah[ks][2], ah[ks][3], e0, e1);
                mma_bf16(ob, ah[ks][0], ah[ks][1], ah[ks][2], ah[ks][3], e2, e3);
            }
        }
    }

    l_a += __shfl_xor_sync(0xffffffffu, l_a, 1);
    l_a += __shfl_xor_sync(0xffffffffu, l_a, 2);
    l_b += __shfl_xor_sync(0xffffffffu, l_b, 1);
    l_b += __shfl_xor_sync(0xffffffffu, l_b, 2);
    float inva = 1.f / l_a;
    float invb = 1.f / l_b;

    {
        uint32_t* OH = (uint32_t*)g_ohi;
        uint32_t* OL = (uint32_t*)g_olo;
        size_t rowA = (size_t)bh * SEQ + qt * 128 + 16 * w + g;
        size_t b1 = rowA * 64 + cq;
        size_t b2 = (rowA + 8) * 64 + cq;
        #pragma unroll
        for (int n = 0; n < 16; n++) {
            uint32_t h, lo;
            packsplit(o[n][0] * inva, o[n][1] * inva, h, lo);
            OH[b1 + 4 * n] = h; OL[b1 + 4 * n] = lo;
            packsplit(o[n][2] * invb, o[n][3] * invb, h, lo);
            OH[b2 + 4 * n] = h; OL[b2 + 4 * n] = lo;
        }
    }
}

// ------------------------------------------------------------------
// Kernel 3: output projection with HMMA.
// CTA: 128 rows x 64 cols, K=1024 looped in 8 chunks (one head each).
// ------------------------------------------------------------------
#define WST 144                          // 64 bf16 + 8 pad, bytes
#define OP_AHI 0
#define OP_ALO 34816
#define OP_WHI 69632
#define OP_WLO 88064
#define OPROJ_SMEM 106496

__global__ __launch_bounds__(256, 1) void oproj_kernel(
    const float* __restrict__ Wo, const float* __restrict__ bo,
    float* __restrict__ out)
{
    extern __shared__ char smem[];
    const uint32_t sb = smem_u32(smem);
    const int tid = threadIdx.x;
    const int gc0 = (int)blockIdx.x * 64;
    const int gr0 = (int)blockIdx.y * 128;
    const int bb = gr0 >> 11, ss0 = gr0 & 2047;

    const int w    = tid >> 5;
    const int lane = tid & 31;
    const int g    = lane >> 2;
    const int cq   = lane & 3;

    const uint32_t loffA = (uint32_t)((16 * w + (lane & 15)) * PST + (lane >> 4) * 16);
    const uint32_t loffB = (uint32_t)((lane & 7) * WST + ((lane >> 3) & 1) * 8 * WST
                                      + (lane >> 4) * 16);

    float c[8][4];
    #pragma unroll
    for (int n = 0; n < 8; n++) { c[n][0] = c[n][1] = c[n][2] = c[n][3] = 0.f; }

    for (int kc = 0; kc < 8; kc++) {
        if (kc) __syncthreads();
        // stage A (attn out hi/lo) for head kc: 128 rows x 128 d
        {
            const uint4* Ah = (const uint4*)g_ohi + ((size_t)(bb * H + kc) * SEQ + ss0) * 16;
            const uint4* Al = (const uint4*)g_olo + ((size_t)(bb * H + kc) * SEQ + ss0) * 16;
            #pragma unroll
            for (int i = 0; i < 8; i++) {
                int idx = tid + i * 256;
                int r = idx >> 4, q = idx & 15;
                *(uint4*)(smem + OP_AHI + r * PST + q * 16) = Ah[r * 16 + q];
                *(uint4*)(smem + OP_ALO + r * PST + q * 16) = Al[r * 16 + q];
            }
        }
        // stage Wo chunk [k=128][n=64] (fp32 -> hi/lo)
        #pragma unroll
        for (int i = 0; i < 8; i++) {
            int idx = tid + i * 256;
            int k = idx >> 4, ng = (idx & 15) << 2;
            float4 t = *(const float4*)&Wo[(size_t)(kc * 128 + k) * DM + gc0 + ng];
            uint2 h2, l2;
            split4(t.x, t.y, t.z, t.w, h2, l2);
            *(uint2*)(smem + OP_WHI + k * WST + ng * 2) = h2;
            *(uint2*)(smem + OP_WLO + k * WST + ng * 2) = l2;
        }
        __syncthreads();

        #pragma unroll
        for (int ks = 0; ks < 8; ks++) {
            uint32_t ah0, ah1, ah2, ah3, al0, al1, al2, al3;
            ldsm4(sb + OP_AHI + loffA + (uint32_t)(ks * 32), ah0, ah1, ah2, ah3);
            ldsm4(sb + OP_ALO + loffA + (uint32_t)(ks * 32), al0, al1, al2, al3);
            #pragma unroll
            for (int np = 0; np < 4; np++) {
                uint32_t b0, b1, b2, b3, e0, e1, e2, e3;
                uint32_t off = loffB + (uint32_t)(np * 32 + ks * 16 * WST);
                ldsm4t(sb + OP_WHI + off, b0, b1, b2, b3);
                ldsm4t(sb + OP_WLO + off, e0, e1, e2, e3);
                float* ca = c[2 * np];
                float* cb = c[2 * np + 1];
                mma_bf16(ca, ah0, ah1, ah2, ah3, b0, b1);
                mma_bf16(ca, al0, al1, al2, al3, b0, b1);
                mma_bf16(ca, ah0, ah1, ah2, ah3, e0, e1);
                mma_bf16(cb, ah0, ah1, ah2, ah3, b2, b3);
                mma_bf16(cb, al0, al1, al2, al3, b2, b3);
                mma_bf16(cb, ah0, ah1, ah2, ah3, e2, e3);
            }
        }
    }

    // epilogue: bias + fp32 store
    const int r1 = gr0 + 16 * w + g;
    #pragma unroll
    for (int nt = 0; nt < 8; nt++) {
        int col = gc0 + nt * 8 + 2 * cq;
        float2 bi = *(const float2*)&bo[col];
        *(float2*)&out[(size_t)r1 * DM + col] =
            make_float2(c[nt][0] + bi.x, c[nt][1] + bi.y);
        *(float2*)&out[(size_t)(r1 + 8) * DM + col] =
            make_float2(c[nt][2] + bi.x, c[nt][3] + bi.y);
    }
}

// ------------------------------------------------------------------
extern "C" void kernel_launch(void* const* d_in, const int* in_sizes, int n_in,
                              void* d_out, int out_size)
{
    const float* query = (const float*)d_in[0];
    const float* key   = (const float*)d_in[1];
    const float* value = (const float*)d_in[2];
    // d_in[3] = mask (tril, analytic)
    const float* Wq = (const float*)d_in[4];
    const float* bq = (const float*)d_in[5];
    const float* Wk = (const float*)d_in[6];
    const float* bk = (const float*)d_in[7];
    const float* Wv = (const float*)d_in[8];
    const float* bv = (const float*)d_in[9];
    const float* Wo = (const float*)d_in[10];
    const float* bo = (const float*)d_in[11];
    float* out = (float*)d_out;

    cudaFuncSetAttribute(proj_kernel, cudaFuncAttributeMaxDynamicSharedMemorySize, PROJ_SMEM);
    cudaFuncSetAttribute(attn_kernel, cudaFuncAttributeMaxDynamicSharedMemorySize, ATTN_SMEM);
    cudaFuncSetAttribute(oproj_kernel, cudaFuncAttributeMaxDynamicSharedMemorySize, OPROJ_SMEM);

    rope_table_kernel<<<512, 256>>>();
    proj_kernel<<<dim3(8, 64, 3), 256, PROJ_SMEM>>>(query, key, value,
                                                    Wq, bq, Wk, bk, Wv, bv);
    attn_kernel<<<dim3(16, 32), 256, ATTN_SMEM>>>();
    oproj_kernel<<<dim3(2, 64), 256, OPROJ_SMEM>>>(Wo, bo, out);
}

// round 6
// speedup vs baseline: 20.8912x; 1.0465x over previous
#include <cuda_runtime.h>
#include <cuda_bf16.h>
#include <math.h>
#include <stdint.h>

#define B 4
#define SEQ 2048
#define DM 128
#define H 8
#define DI 1024

// Global scratch (static __device__, no allocation). Row-major [bh][s][d].
__device__ __align__(16) __nv_bfloat16 g_qhi[B*H*SEQ*DM];
__device__ __align__(16) __nv_bfloat16 g_qlo[B*H*SEQ*DM];
__device__ __align__(16) __nv_bfloat16 g_khi[B*H*SEQ*DM];
__device__ __align__(16) __nv_bfloat16 g_klo[B*H*SEQ*DM];
__device__ __align__(16) __nv_bfloat16 g_vhi[B*H*SEQ*DM];
__device__ __align__(16) __nv_bfloat16 g_vlo[B*H*SEQ*DM];
__device__ __align__(16) __nv_bfloat16 g_ohi[B*H*SEQ*DM];
__device__ __align__(16) __nv_bfloat16 g_olo[B*H*SEQ*DM];
__device__ __align__(8)  float2 g_rope[SEQ*64];   // (cos, sin) per (pos, dpair)

// ------------------------------------------------------------------
// helpers
// ------------------------------------------------------------------
__device__ __forceinline__ uint32_t smem_u32(const void* p) {
    uint32_t a;
    asm("{ .reg .u64 t; cvta.to.shared.u64 t, %1; cvt.u32.u64 %0, t; }" : "=r"(a) : "l"(p));
    return a;
}
__device__ __forceinline__ void mma_bf16(float c[4], uint32_t a0, uint32_t a1,
                                         uint32_t a2, uint32_t a3,
                                         uint32_t b0, uint32_t b1) {
    asm volatile(
        "mma.sync.aligned.m16n8k16.row.col.f32.bf16.bf16.f32 "
        "{%0,%1,%2,%3}, {%4,%5,%6,%7}, {%8,%9}, {%0,%1,%2,%3};"
        : "+f"(c[0]), "+f"(c[1]), "+f"(c[2]), "+f"(c[3])
        : "r"(a0), "r"(a1), "r"(a2), "r"(a3), "r"(b0), "r"(b1));
}
__device__ __forceinline__ void ldsm4(uint32_t addr, uint32_t& r0, uint32_t& r1,
                                      uint32_t& r2, uint32_t& r3) {
    asm volatile("ldmatrix.sync.aligned.m8n8.x4.shared.b16 {%0,%1,%2,%3}, [%4];"
                 : "=r"(r0), "=r"(r1), "=r"(r2), "=r"(r3) : "r"(addr));
}
__device__ __forceinline__ void ldsm4t(uint32_t addr, uint32_t& r0, uint32_t& r1,
                                       uint32_t& r2, uint32_t& r3) {
    asm volatile("ldmatrix.sync.aligned.m8n8.x4.trans.shared.b16 {%0,%1,%2,%3}, [%4];"
                 : "=r"(r0), "=r"(r1), "=r"(r2), "=r"(r3) : "r"(addr));
}
__device__ __forceinline__ void cp16(uint32_t dst, const void* src) {
    asm volatile("cp.async.cg.shared.global [%0], [%1], 16;" :: "r"(dst), "l"(src));
}
#define CP_COMMIT() asm volatile("cp.async.commit_group;" ::: "memory")
#define CP_WAIT(n)  asm volatile("cp.async.wait_group %0;" :: "n"(n) : "memory")

__device__ __forceinline__ void packsplit(float a, float b, uint32_t& hi, uint32_t& lo) {
    __nv_bfloat162 h = __floats2bfloat162_rn(a, b);
    hi = *(uint32_t*)&h;
    __nv_bfloat162 l = __floats2bfloat162_rn(a - __low2float(h), b - __high2float(h));
    lo = *(uint32_t*)&l;
}
__device__ __forceinline__ void split4(float v0, float v1, float v2, float v3,
                                       uint2& h, uint2& lo) {
    __nv_bfloat162 h01 = __floats2bfloat162_rn(v0, v1);
    __nv_bfloat162 h23 = __floats2bfloat162_rn(v2, v3);
    __nv_bfloat162 l01 = __floats2bfloat162_rn(v0 - __low2float(h01), v1 - __high2float(h01));
    __nv_bfloat162 l23 = __floats2bfloat162_rn(v2 - __low2float(h23), v3 - __high2float(h23));
    h  = make_uint2(*(uint32_t*)&h01, *(uint32_t*)&h23);
    lo = make_uint2(*(uint32_t*)&l01, *(uint32_t*)&l23);
}

// Accurate sincos (double-assisted range reduction; fast-math immune)
__device__ __forceinline__ void sincos_acc(float x, float* so, float* co) {
    double td = (double)x;
    int qi = __double2int_rn(td * 0.63661977236758138);
    float r = (float)(td - (double)qi * 1.5707963267948966);
    float r2 = r * r;
    float sp = fmaf(r2, -1.9840874e-4f, 8.3333310e-3f);
    sp = fmaf(r2, sp, -1.6666667e-1f);
    sp = fmaf(r * r2, sp, r);
    float cp = fmaf(r2, 2.4760495e-5f, -1.3888397e-3f);
    cp = fmaf(r2, cp, 4.16666418e-2f);
    cp = fmaf(r2, cp, -0.5f);
    cp = fmaf(r2, cp, 1.0f);
    int n = qi & 3;
    float s = sp, c = cp;
    if (n & 1) { float t = s; s = c; c = -t; }
    if (n & 2) { s = -s; c = -c; }
    *so = s; *co = c;
}

// ------------------------------------------------------------------
// Kernel 0: RoPE table  (cos,sin)[pos][dpair]
// ------------------------------------------------------------------
__global__ __launch_bounds__(256) void rope_table_kernel()
{
    int idx = blockIdx.x * 256 + threadIdx.x;   // 0..131071
    int ss = idx >> 6, dp = idx & 63;
    const double c13 = 13.287712379549449 / 128.0;  // log2(10000)/128
    float invf = (float)exp2(-(double)(2 * dp) * c13);
    float th = (float)ss * invf;
    float s, c;
    sincos_acc(th, &s, &c);
    g_rope[idx] = make_float2(c, s);
}

// ------------------------------------------------------------------
// Kernel 1: QKV projection with HMMA (hi/lo split), epilogue does
// bias + RoPE (+Q pre-scale), writes bf16 hi/lo row-major.
// ------------------------------------------------------------------
#define PST 272                          // 128 bf16 + 8 pad, bytes
#define PJ_XHI 0
#define PJ_XLO 34816
#define PJ_WHI 69632
#define PJ_WLO 104448
#define PROJ_SMEM 139264

__global__ __launch_bounds__(256, 1) void proj_kernel(
    const float* __restrict__ xq, const float* __restrict__ xk, const float* __restrict__ xv,
    const float* __restrict__ Wq, const float* __restrict__ bq,
    const float* __restrict__ Wk, const float* __restrict__ bk,
    const float* __restrict__ Wv, const float* __restrict__ bv)
{
    extern __shared__ char smem[];
    const uint32_t sb = smem_u32(smem);
    const int which = blockIdx.z;
    const float* X    = (which == 0) ? xq : (which == 1) ? xk : xv;
    const float* W    = (which == 0) ? Wq : (which == 1) ? Wk : Wv;
    const float* bias = (which == 0) ? bq : (which == 1) ? bk : bv;
    uint32_t* OH = (uint32_t*)((which == 0) ? g_qhi : (which == 1) ? g_khi : g_vhi);
    uint32_t* OL = (uint32_t*)((which == 0) ? g_qlo : (which == 1) ? g_klo : g_vlo);

    const int tid = threadIdx.x;
    const int hh  = blockIdx.x;
    const int gc0 = hh * 128;
    const int gr0 = (int)blockIdx.y * 128;

    #pragma unroll
    for (int i = 0; i < 16; i++) {
        int idx = tid + i * 256;
        int row = idx >> 5, c4 = (idx & 31) << 2;
        float4 t = *(const float4*)&X[(size_t)(gr0 + row) * DM + c4];
        uint2 h2, l2;
        split4(t.x, t.y, t.z, t.w, h2, l2);
        *(uint2*)(smem + PJ_XHI + row * PST + c4 * 2) = h2;
        *(uint2*)(smem + PJ_XLO + row * PST + c4 * 2) = l2;
    }
    #pragma unroll
    for (int i = 0; i < 16; i++) {
        int idx = tid + i * 256;
        int k = idx >> 5, ng = (idx & 31) << 2;
        float4 t = *(const float4*)&W[(size_t)k * DI + gc0 + ng];
        uint2 h2, l2;
        split4(t.x, t.y, t.z, t.w, h2, l2);
        *(uint2*)(smem + PJ_WHI + k * PST + ng * 2) = h2;
        *(uint2*)(smem + PJ_WLO + k * PST + ng * 2) = l2;
    }
    __syncthreads();

    const int w    = tid >> 5;
    const int lane = tid & 31;
    const int g    = lane >> 2;
    const int cq   = lane & 3;

    const uint32_t loffA = (uint32_t)((16 * w + (lane & 15)) * PST + (lane >> 4) * 16);
    const uint32_t loffB = (uint32_t)((lane & 7) * PST + ((lane >> 3) & 1) * 8 * PST
                                      + (lane >> 4) * 16);

    float c[16][4];
    #pragma unroll
    for (int n = 0; n < 16; n++) { c[n][0] = c[n][1] = c[n][2] = c[n][3] = 0.f; }

    #pragma unroll
    for (int ks = 0; ks < 8; ks++) {
        uint32_t ah0, ah1, ah2, ah3, al0, al1, al2, al3;
        ldsm4(sb + PJ_XHI + loffA + (uint32_t)(ks * 32), ah0, ah1, ah2, ah3);
        ldsm4(sb + PJ_XLO + loffA + (uint32_t)(ks * 32), al0, al1, al2, al3);
        #pragma unroll
        for (int np = 0; np < 8; np++) {
            uint32_t b0, b1, b2, b3, e0, e1, e2, e3;
            uint32_t off = loffB + (uint32_t)(np * 32 + ks * 16 * PST);
            ldsm4t(sb + PJ_WHI + off, b0, b1, b2, b3);
            ldsm4t(sb + PJ_WLO + off, e0, e1, e2, e3);
            float* ca = c[2 * np];
            float* cb = c[2 * np + 1];
            mma_bf16(ca, ah0, ah1, ah2, ah3, b0, b1);
            mma_bf16(ca, al0, al1, al2, al3, b0, b1);
            mma_bf16(ca, ah0, ah1, ah2, ah3, e0, e1);
            mma_bf16(cb, ah0, ah1, ah2, ah3, b2, b3);
            mma_bf16(cb, al0, al1, al2, al3, b2, b3);
            mma_bf16(cb, ah0, ah1, ah2, ah3, e2, e3);
        }
    }

    const int gr = gr0 + 16 * w + g;
    const int bb = gr >> 11, ss = gr & 2047;
    const size_t row1 = (size_t)(bb * H + hh) * SEQ + ss;
    const float QSCL = 0.08838834764831845f;

    #pragma unroll
    for (int nt = 0; nt < 16; nt++) {
        int d = nt * 8 + 2 * cq;
        float2 bi = *(const float2*)&bias[gc0 + d];
        float v0 = c[nt][0] + bi.x, v1 = c[nt][1] + bi.y;
        float v2 = c[nt][2] + bi.x, v3 = c[nt][3] + bi.y;
        if (which < 2) {
            int dp = nt * 4 + cq;
            float2 t1 = g_rope[ss * 64 + dp];
            float2 t2 = g_rope[(ss + 8) * 64 + dp];
            float o0 = v0 * t1.x - v1 * t1.y;
            float o1 = v1 * t1.x + v0 * t1.y;
            float o2 = v2 * t2.x - v3 * t2.y;
            float o3 = v3 * t2.x + v2 * t2.y;
            v0 = o0; v1 = o1; v2 = o2; v3 = o3;
            if (which == 0) { v0 *= QSCL; v1 *= QSCL; v2 *= QSCL; v3 *= QSCL; }
        }
        uint32_t h, lo;
        int dp = nt * 4 + cq;
        packsplit(v0, v1, h, lo);
        OH[row1 * 64 + dp] = h;
        OL[row1 * 64 + dp] = lo;
        packsplit(v2, v3, h, lo);
        OH[(row1 + 8) * 64 + dp] = h;
        OL[(row1 + 8) * 64 + dp] = lo;
    }
}

// ------------------------------------------------------------------
// Kernel 2: causal flash attention (HMMA hi/lo) with 2-stage
// cp.async double-buffered K/V staging.
// ------------------------------------------------------------------
#define KVSTRIDE 272
#define OFF_KH 0
#define OFF_KL (64 * KVSTRIDE)
#define OFF_VH (2 * 64 * KVSTRIDE)
#define OFF_VL (3 * 64 * KVSTRIDE)
#define STAGE   (4 * 64 * KVSTRIDE)      // 69632 B
#define ATTN_SMEM (2 * STAGE)            // 139264 B

__device__ __forceinline__ void cp_tile(uint32_t dstbase, int tid, int bh, int kt)
{
    size_t srcbase = ((size_t)bh * SEQ + (size_t)kt * 64) * 16;   // uint4 units
    const uint4* kh4 = (const uint4*)g_khi + srcbase;
    const uint4* kl4 = (const uint4*)g_klo + srcbase;
    const uint4* vh4 = (const uint4*)g_vhi + srcbase;
    const uint4* vl4 = (const uint4*)g_vlo + srcbase;
    #pragma unroll
    for (int i = 0; i < 4; i++) {
        int x = tid + i * 256;
        int row = x >> 4, c = x & 15;
        uint32_t doff = (uint32_t)(row * KVSTRIDE + c * 16);
        int sidx = row * 16 + c;
        cp16(dstbase + OFF_KH + doff, kh4 + sidx);
        cp16(dstbase + OFF_KL + doff, kl4 + sidx);
        cp16(dstbase + OFF_VH + doff, vh4 + sidx);
        cp16(dstbase + OFF_VL + doff, vl4 + sidx);
    }
}

__global__ __launch_bounds__(256, 1) void attn_kernel()
{
    extern __shared__ char smem[];
    const uint32_t sb = smem_u32(smem);
    const int tid  = threadIdx.x;
    const int w    = tid >> 5;
    const int lane = tid & 31;
    const int bh   = blockIdx.y;
    const int qt   = 15 - (int)blockIdx.x;

    const int g  = lane >> 2;
    const int cq = lane & 3;
    const int nkt = 2 * qt + 2;

    // prefetch tile 0 into stage 0
    cp_tile(sb, tid, bh, 0);
    CP_COMMIT();

    uint32_t qh[8][4], ql[8][4];
    {
        const uint32_t* Qh32 = (const uint32_t*)g_qhi;
        const uint32_t* Ql32 = (const uint32_t*)g_qlo;
        size_t rowA = (size_t)bh * SEQ + qt * 128 + 16 * w + g;
        size_t rowB = rowA + 8;
        #pragma unroll
        for (int j = 0; j < 8; j++) {
            int cA = (cq << 1) + 16 * j;
            size_t iA = rowA * 64 + (cA >> 1);
            size_t iB = rowB * 64 + (cA >> 1);
            qh[j][0] = Qh32[iA];     qh[j][1] = Qh32[iB];
            qh[j][2] = Qh32[iA + 4]; qh[j][3] = Qh32[iB + 4];
            ql[j][0] = Ql32[iA];     ql[j][1] = Ql32[iB];
            ql[j][2] = Ql32[iA + 4]; ql[j][3] = Ql32[iB + 4];
        }
    }

    const uint32_t loffK = (uint32_t)((lane & 7) * KVSTRIDE + (lane >> 3) * 16);
    const uint32_t loffV = (uint32_t)((lane & 7) * KVSTRIDE + ((lane >> 3) & 1) * 8 * KVSTRIDE
                                      + (lane >> 4) * 16);

    float o[16][4];
    #pragma unroll
    for (int n = 0; n < 16; n++)
        #pragma unroll
        for (int i = 0; i < 4; i++) o[n][i] = 0.f;
    float l_a = 0.f, l_b = 0.f;

    const int rowAg = qt * 128 + 16 * w + g;

    for (int kt = 0; kt < nkt; kt++) {
        // prefetch next tile into the other stage
        if (kt + 1 < nkt) {
            cp_tile(sb + (uint32_t)(((kt + 1) & 1) * STAGE), tid, bh, kt + 1);
            CP_COMMIT();
            CP_WAIT(1);
        } else {
            CP_WAIT(0);
        }
        __syncthreads();

        const uint32_t cb = sb + (uint32_t)((kt & 1) * STAGE);

        // ---- S = Q K^T (3-product hi/lo) ----
        float sfrag[8][4];
        #pragma unroll
        for (int nt = 0; nt < 8; nt++) {
            float* c = sfrag[nt];
            c[0] = c[1] = c[2] = c[3] = 0.f;
            uint32_t baseH = cb + OFF_KH + (uint32_t)(nt * 8 * KVSTRIDE) + loffK;
            uint32_t baseL = cb + OFF_KL + (uint32_t)(nt * 8 * KVSTRIDE) + loffK;
            #pragma unroll
            for (int kk = 0; kk < 4; kk++) {
                uint32_t h0, h1, h2, h3, e0, e1, e2, e3;
                ldsm4(baseH + (uint32_t)(kk * 64), h0, h1, h2, h3);
                ldsm4(baseL + (uint32_t)(kk * 64), e0, e1, e2, e3);
                int j = 2 * kk;
                mma_bf16(c, qh[j][0], qh[j][1], qh[j][2], qh[j][3], h0, h1);
                mma_bf16(c, qh[j+1][0], qh[j+1][1], qh[j+1][2], qh[j+1][3], h2, h3);
                mma_bf16(c, ql[j][0], ql[j][1], ql[j][2], ql[j][3], h0, h1);
                mma_bf16(c, ql[j+1][0], ql[j+1][1], ql[j+1][2], ql[j+1][3], h2, h3);
                mma_bf16(c, qh[j][0], qh[j][1], qh[j][2], qh[j][3], e0, e1);
                mma_bf16(c, qh[j+1][0], qh[j+1][1], qh[j+1][2], qh[j+1][3], e2, e3);
            }
        }

        // ---- softmax + causal mask ----
        const bool diag = (kt >= 2 * qt);
        const int colb = kt * 64 + 2 * cq;
        float lsa = 0.f, lsb = 0.f;
        #pragma unroll
        for (int nt = 0; nt < 8; nt++) {
            float* c = sfrag[nt];
            float p0 = __expf(c[0]);
            float p1 = __expf(c[1]);
            float p2 = __expf(c[2]);
            float p3 = __expf(c[3]);
            if (diag) {
                int cc = colb + 8 * nt;
                if (cc     > rowAg)     p0 = 0.f;
                if (cc + 1 > rowAg)     p1 = 0.f;
                if (cc     > rowAg + 8) p2 = 0.f;
                if (cc + 1 > rowAg + 8) p3 = 0.f;
            }
            c[0] = p0; c[1] = p1; c[2] = p2; c[3] = p3;
            lsa += p0 + p1;
            lsb += p2 + p3;
        }
        l_a += lsa;
        l_b += lsb;

        uint32_t ah[4][4], al[4][4];
        #pragma unroll
        for (int ks = 0; ks < 4; ks++) {
            packsplit(sfrag[2*ks][0],   sfrag[2*ks][1],   ah[ks][0], al[ks][0]);
            packsplit(sfrag[2*ks][2],   sfrag[2*ks][3],   ah[ks][1], al[ks][1]);
            packsplit(sfrag[2*ks+1][0], sfrag[2*ks+1][1], ah[ks][2], al[ks][2]);
            packsplit(sfrag[2*ks+1][2], sfrag[2*ks+1][3], ah[ks][3], al[ks][3]);
        }

        // ---- O += P V (3-product hi/lo) ----
        #pragma unroll
        for (int np = 0; np < 8; np++) {
            uint32_t baseH = cb + OFF_VH + (uint32_t)(np * 32) + loffV;
            uint32_t baseL = cb + OFF_VL + (uint32_t)(np * 32) + loffV;
            float* oa = o[2 * np];
            float* ob = o[2 * np + 1];
            #pragma unroll
            for (int ks = 0; ks < 4; ks++) {
                uint32_t h0, h1, h2, h3, e0, e1, e2, e3;
                ldsm4t(baseH + (uint32_t)(ks * 16 * KVSTRIDE), h0, h1, h2, h3);
                ldsm4t(baseL + (uint32_t)(ks * 16 * KVSTRIDE), e0, e1, e2, e3);
                mma_bf16(oa, ah[ks][0], ah[ks][1], ah[ks][2], ah[ks][3], h0, h1);
                mma_bf16(ob, ah[ks][0], ah[ks][1], ah[ks][2], ah[ks][3], h2, h3);
                mma_bf16(oa, al[ks][0], al[ks][1], al[ks][2], al[ks][3], h0, h1);
                mma_bf16(ob, al[ks][0], al[ks][1], al[ks][2], al[ks][3], h2, h3);
                mma_bf16(oa, ah[ks][0], ah[ks][1], ah[ks][2], ah[ks][3], e0, e1);
                mma_bf16(ob, ah[ks][0], ah[ks][1], ah[ks][2], ah[ks][3], e2, e3);
            }
        }
        __syncthreads();   // protect stage being refilled next iteration
    }

    l_a += __shfl_xor_sync(0xffffffffu, l_a, 1);
    l_a += __shfl_xor_sync(0xffffffffu, l_a, 2);
    l_b += __shfl_xor_sync(0xffffffffu, l_b, 1);
    l_b += __shfl_xor_sync(0xffffffffu, l_b, 2);
    float inva = 1.f / l_a;
    float invb = 1.f / l_b;

    {
        uint32_t* OH = (uint32_t*)g_ohi;
        uint32_t* OL = (uint32_t*)g_olo;
        size_t rowA = (size_t)bh * SEQ + qt * 128 + 16 * w + g;
        size_t b1 = rowA * 64 + cq;
        size_t b2 = (rowA + 8) * 64 + cq;
        #pragma unroll
        for (int n = 0; n < 16; n++) {
            uint32_t h, lo;
            packsplit(o[n][0] * inva, o[n][1] * inva, h, lo);
            OH[b1 + 4 * n] = h; OL[b1 + 4 * n] = lo;
            packsplit(o[n][2] * invb, o[n][3] * invb, h, lo);
            OH[b2 + 4 * n] = h; OL[b2 + 4 * n] = lo;
        }
    }
}

// ------------------------------------------------------------------
// Kernel 3: output projection with HMMA.
// ------------------------------------------------------------------
#define WST 144                          // 64 bf16 + 8 pad, bytes
#define OP_AHI 0
#define OP_ALO 34816
#define OP_WHI 69632
#define OP_WLO 88064
#define OPROJ_SMEM 106496

__global__ __launch_bounds__(256, 1) void oproj_kernel(
    const float* __restrict__ Wo, const float* __restrict__ bo,
    float* __restrict__ out)
{
    extern __shared__ char smem[];
    const uint32_t sb = smem_u32(smem);
    const int tid = threadIdx.x;
    const int gc0 = (int)blockIdx.x * 64;
    const int gr0 = (int)blockIdx.y * 128;
    const int bb = gr0 >> 11, ss0 = gr0 & 2047;

    const int w    = tid >> 5;
    const int lane = tid & 31;
    const int g    = lane >> 2;
    const int cq   = lane & 3;

    const uint32_t loffA = (uint32_t)((16 * w + (lane & 15)) * PST + (lane >> 4) * 16);
    const uint32_t loffB = (uint32_t)((lane & 7) * WST + ((lane >> 3) & 1) * 8 * WST
                                      + (lane >> 4) * 16);

    float c[8][4];
    #pragma unroll
    for (int n = 0; n < 8; n++) { c[n][0] = c[n][1] = c[n][2] = c[n][3] = 0.f; }

    for (int kc = 0; kc < 8; kc++) {
        if (kc) __syncthreads();
        {
            const uint4* Ah = (const uint4*)g_ohi + ((size_t)(bb * H + kc) * SEQ + ss0) * 16;
            const uint4* Al = (const uint4*)g_olo + ((size_t)(bb * H + kc) * SEQ + ss0) * 16;
            #pragma unroll
            for (int i = 0; i < 8; i++) {
                int idx = tid + i * 256;
                int r = idx >> 4, q = idx & 15;
                *(uint4*)(smem + OP_AHI + r * PST + q * 16) = Ah[r * 16 + q];
                *(uint4*)(smem + OP_ALO + r * PST + q * 16) = Al[r * 16 + q];
            }
        }
        #pragma unroll
        for (int i = 0; i < 8; i++) {
            int idx = tid + i * 256;
            int k = idx >> 4, ng = (idx & 15) << 2;
            float4 t = *(const float4*)&Wo[(size_t)(kc * 128 + k) * DM + gc0 + ng];
            uint2 h2, l2;
            split4(t.x, t.y, t.z, t.w, h2, l2);
            *(uint2*)(smem + OP_WHI + k * WST + ng * 2) = h2;
            *(uint2*)(smem + OP_WLO + k * WST + ng * 2) = l2;
        }
        __syncthreads();

        #pragma unroll
        for (int ks = 0; ks < 8; ks++) {
            uint32_t ah0, ah1, ah2, ah3, al0, al1, al2, al3;
            ldsm4(sb + OP_AHI + loffA + (uint32_t)(ks * 32), ah0, ah1, ah2, ah3);
            ldsm4(sb + OP_ALO + loffA + (uint32_t)(ks * 32), al0, al1, al2, al3);
            #pragma unroll
            for (int np = 0; np < 4; np++) {
                uint32_t b0, b1, b2, b3, e0, e1, e2, e3;
                uint32_t off = loffB + (uint32_t)(np * 32 + ks * 16 * WST);
                ldsm4t(sb + OP_WHI + off, b0, b1, b2, b3);
                ldsm4t(sb + OP_WLO + off, e0, e1, e2, e3);
                float* ca = c[2 * np];
                float* cb = c[2 * np + 1];
                mma_bf16(ca, ah0, ah1, ah2, ah3, b0, b1);
                mma_bf16(ca, al0, al1, al2, al3, b0, b1);
                mma_bf16(ca, ah0, ah1, ah2, ah3, e0, e1);
                mma_bf16(cb, ah0, ah1, ah2, ah3, b2, b3);
                mma_bf16(cb, al0, al1, al2, al3, b2, b3);
                mma_bf16(cb, ah0, ah1, ah2, ah3, e2, e3);
            }
        }
    }

    const int r1 = gr0 + 16 * w + g;
    #pragma unroll
    for (int nt = 0; nt < 8; nt++) {
        int col = gc0 + nt * 8 + 2 * cq;
        float2 bi = *(const float2*)&bo[col];
        *(float2*)&out[(size_t)r1 * DM + col] =
            make_float2(c[nt][0] + bi.x, c[nt][1] + bi.y);
        *(float2*)&out[(size_t)(r1 + 8) * DM + col] =
            make_float2(c[nt][2] + bi.x, c[nt][3] + bi.y);
    }
}

// ------------------------------------------------------------------
extern "C" void kernel_launch(void* const* d_in, const int* in_sizes, int n_in,
                              void* d_out, int out_size)
{
    const float* query = (const float*)d_in[0];
    const float* key   = (const float*)d_in[1];
    const float* value = (const float*)d_in[2];
    // d_in[3] = mask (tril, analytic)
    const float* Wq = (const float*)d_in[4];
    const float* bq = (const float*)d_in[5];
    const float* Wk = (const float*)d_in[6];
    const float* bk = (const float*)d_in[7];
    const float* Wv = (const float*)d_in[8];
    const float* bv = (const float*)d_in[9];
    const float* Wo = (const float*)d_in[10];
    const float* bo = (const float*)d_in[11];
    float* out = (float*)d_out;

    cudaFuncSetAttribute(proj_kernel, cudaFuncAttributeMaxDynamicSharedMemorySize, PROJ_SMEM);
    cudaFuncSetAttribute(attn_kernel, cudaFuncAttributeMaxDynamicSharedMemorySize, ATTN_SMEM);
    cudaFuncSetAttribute(oproj_kernel, cudaFuncAttributeMaxDynamicSharedMemorySize, OPROJ_SMEM);

    rope_table_kernel<<<512, 256>>>();
    proj_kernel<<<dim3(8, 64, 3), 256, PROJ_SMEM>>>(query, key, value,
                                                    Wq, bq, Wk, bk, Wv, bv);
    attn_kernel<<<dim3(16, 32), 256, ATTN_SMEM>>>();
    oproj_kernel<<<dim3(2, 64), 256, OPROJ_SMEM>>>(Wo, bo, out);
}

// round 7
// speedup vs baseline: 21.1151x; 1.0107x over previous
#include <cuda_runtime.h>
#include <cuda_bf16.h>
#include <math.h>
#include <stdint.h>

#define B 4
#define SEQ 2048
#define DM 128
#define H 8
#define DI 1024

// Global scratch (static __device__, no allocation). Row-major [bh][s][d].
__device__ __align__(16) __nv_bfloat16 g_qhi[B*H*SEQ*DM];
__device__ __align__(16) __nv_bfloat16 g_qlo[B*H*SEQ*DM];
__device__ __align__(16) __nv_bfloat16 g_khi[B*H*SEQ*DM];
__device__ __align__(16) __nv_bfloat16 g_klo[B*H*SEQ*DM];
__device__ __align__(16) __nv_bfloat16 g_vhi[B*H*SEQ*DM];
__device__ __align__(16) __nv_bfloat16 g_vlo[B*H*SEQ*DM];
__device__ __align__(16) __nv_bfloat16 g_ohi[B*H*SEQ*DM];
__device__ __align__(16) __nv_bfloat16 g_olo[B*H*SEQ*DM];
__device__ __align__(8)  float2 g_rope[SEQ*64];   // (cos, sin) per (pos, dpair)

// ------------------------------------------------------------------
// helpers
// ------------------------------------------------------------------
__device__ __forceinline__ uint32_t smem_u32(const void* p) {
    uint32_t a;
    asm("{ .reg .u64 t; cvta.to.shared.u64 t, %1; cvt.u32.u64 %0, t; }" : "=r"(a) : "l"(p));
    return a;
}
__device__ __forceinline__ void mma_bf16(float c[4], uint32_t a0, uint32_t a1,
                                         uint32_t a2, uint32_t a3,
                                         uint32_t b0, uint32_t b1) {
    asm volatile(
        "mma.sync.aligned.m16n8k16.row.col.f32.bf16.bf16.f32 "
        "{%0,%1,%2,%3}, {%4,%5,%6,%7}, {%8,%9}, {%0,%1,%2,%3};"
        : "+f"(c[0]), "+f"(c[1]), "+f"(c[2]), "+f"(c[3])
        : "r"(a0), "r"(a1), "r"(a2), "r"(a3), "r"(b0), "r"(b1));
}
__device__ __forceinline__ void ldsm4(uint32_t addr, uint32_t& r0, uint32_t& r1,
                                      uint32_t& r2, uint32_t& r3) {
    asm volatile("ldmatrix.sync.aligned.m8n8.x4.shared.b16 {%0,%1,%2,%3}, [%4];"
                 : "=r"(r0), "=r"(r1), "=r"(r2), "=r"(r3) : "r"(addr));
}
__device__ __forceinline__ void ldsm4t(uint32_t addr, uint32_t& r0, uint32_t& r1,
                                       uint32_t& r2, uint32_t& r3) {
    asm volatile("ldmatrix.sync.aligned.m8n8.x4.trans.shared.b16 {%0,%1,%2,%3}, [%4];"
                 : "=r"(r0), "=r"(r1), "=r"(r2), "=r"(r3) : "r"(addr));
}
__device__ __forceinline__ void cp16(uint32_t dst, const void* src) {
    asm volatile("cp.async.cg.shared.global [%0], [%1], 16;" :: "r"(dst), "l"(src));
}
#define CP_COMMIT() asm volatile("cp.async.commit_group;" ::: "memory")
#define CP_WAIT(n)  asm volatile("cp.async.wait_group %0;" :: "n"(n) : "memory")

__device__ __forceinline__ void packsplit(float a, float b, uint32_t& hi, uint32_t& lo) {
    __nv_bfloat162 h = __floats2bfloat162_rn(a, b);
    hi = *(uint32_t*)&h;
    __nv_bfloat162 l = __floats2bfloat162_rn(a - __low2float(h), b - __high2float(h));
    lo = *(uint32_t*)&l;
}
__device__ __forceinline__ void split4(float v0, float v1, float v2, float v3,
                                       uint2& h, uint2& lo) {
    __nv_bfloat162 h01 = __floats2bfloat162_rn(v0, v1);
    __nv_bfloat162 h23 = __floats2bfloat162_rn(v2, v3);
    __nv_bfloat162 l01 = __floats2bfloat162_rn(v0 - __low2float(h01), v1 - __high2float(h01));
    __nv_bfloat162 l23 = __floats2bfloat162_rn(v2 - __low2float(h23), v3 - __high2float(h23));
    h  = make_uint2(*(uint32_t*)&h01, *(uint32_t*)&h23);
    lo = make_uint2(*(uint32_t*)&l01, *(uint32_t*)&l23);
}

// Accurate sincos (double-assisted range reduction; fast-math immune)
__device__ __forceinline__ void sincos_acc(float x, float* so, float* co) {
    double td = (double)x;
    int qi = __double2int_rn(td * 0.63661977236758138);
    float r = (float)(td - (double)qi * 1.5707963267948966);
    float r2 = r * r;
    float sp = fmaf(r2, -1.9840874e-4f, 8.3333310e-3f);
    sp = fmaf(r2, sp, -1.6666667e-1f);
    sp = fmaf(r * r2, sp, r);
    float cp = fmaf(r2, 2.4760495e-5f, -1.3888397e-3f);
    cp = fmaf(r2, cp, 4.16666418e-2f);
    cp = fmaf(r2, cp, -0.5f);
    cp = fmaf(r2, cp, 1.0f);
    int n = qi & 3;
    float s = sp, c = cp;
    if (n & 1) { float t = s; s = c; c = -t; }
    if (n & 2) { s = -s; c = -c; }
    *so = s; *co = c;
}

// ------------------------------------------------------------------
// Kernel 0: RoPE table  (cos,sin)[pos][dpair]
// ------------------------------------------------------------------
__global__ __launch_bounds__(256) void rope_table_kernel()
{
    int idx = blockIdx.x * 256 + threadIdx.x;   // 0..131071
    int ss = idx >> 6, dp = idx & 63;
    const double c13 = 13.287712379549449 / 128.0;  // log2(10000)/128
    float invf = (float)exp2(-(double)(2 * dp) * c13);
    float th = (float)ss * invf;
    float s, c;
    sincos_acc(th, &s, &c);
    g_rope[idx] = make_float2(c, s);
}

// ------------------------------------------------------------------
// Kernel 1: QKV projection with HMMA, CTA tile 128 rows x 64 cols
// (half-head) so 2 CTAs/SM. Epilogue: bias + RoPE (+Q pre-scale).
// grid (16, 64, 3): x = 64-col block (head hh = x>>1, half = x&1).
// ------------------------------------------------------------------
#define PST 272                          // 128 bf16 + 8 pad, bytes
#define WST 144                          // 64 bf16 + 8 pad, bytes
#define PJ_XHI 0
#define PJ_XLO 34816
#define PJ_WHI 69632
#define PJ_WLO 88064
#define PROJ_SMEM 106496

__global__ __launch_bounds__(256, 2) void proj_kernel(
    const float* __restrict__ xq, const float* __restrict__ xk, const float* __restrict__ xv,
    const float* __restrict__ Wq, const float* __restrict__ bq,
    const float* __restrict__ Wk, const float* __restrict__ bk,
    const float* __restrict__ Wv, const float* __restrict__ bv)
{
    extern __shared__ char smem[];
    const uint32_t sb = smem_u32(smem);
    const int which = blockIdx.z;
    const float* X    = (which == 0) ? xq : (which == 1) ? xk : xv;
    const float* W    = (which == 0) ? Wq : (which == 1) ? Wk : Wv;
    const float* bias = (which == 0) ? bq : (which == 1) ? bk : bv;
    uint32_t* OH = (uint32_t*)((which == 0) ? g_qhi : (which == 1) ? g_khi : g_vhi);
    uint32_t* OL = (uint32_t*)((which == 0) ? g_qlo : (which == 1) ? g_klo : g_vlo);

    const int tid = threadIdx.x;
    const int gc0 = (int)blockIdx.x * 64;
    const int hh  = gc0 >> 7;
    const int gr0 = (int)blockIdx.y * 128;

    // ---- stage X tile 128x128 (fp32 -> bf16 hi/lo) ----
    #pragma unroll
    for (int i = 0; i < 16; i++) {
        int idx = tid + i * 256;
        int row = idx >> 5, c4 = (idx & 31) << 2;
        float4 t = *(const float4*)&X[(size_t)(gr0 + row) * DM + c4];
        uint2 h2, l2;
        split4(t.x, t.y, t.z, t.w, h2, l2);
        *(uint2*)(smem + PJ_XHI + row * PST + c4 * 2) = h2;
        *(uint2*)(smem + PJ_XLO + row * PST + c4 * 2) = l2;
    }
    // ---- stage W tile [k=128][n=64] ----
    #pragma unroll
    for (int i = 0; i < 8; i++) {
        int idx = tid + i * 256;
        int k = idx >> 4, ng = (idx & 15) << 2;
        float4 t = *(const float4*)&W[(size_t)k * DI + gc0 + ng];
        uint2 h2, l2;
        split4(t.x, t.y, t.z, t.w, h2, l2);
        *(uint2*)(smem + PJ_WHI + k * WST + ng * 2) = h2;
        *(uint2*)(smem + PJ_WLO + k * WST + ng * 2) = l2;
    }
    __syncthreads();

    const int w    = tid >> 5;
    const int lane = tid & 31;
    const int g    = lane >> 2;
    const int cq   = lane & 3;

    const uint32_t loffA = (uint32_t)((16 * w + (lane & 15)) * PST + (lane >> 4) * 16);
    const uint32_t loffB = (uint32_t)((lane & 7) * WST + ((lane >> 3) & 1) * 8 * WST
                                      + (lane >> 4) * 16);

    float c[8][4];
    #pragma unroll
    for (int n = 0; n < 8; n++) { c[n][0] = c[n][1] = c[n][2] = c[n][3] = 0.f; }

    #pragma unroll
    for (int ks = 0; ks < 8; ks++) {
        uint32_t ah0, ah1, ah2, ah3, al0, al1, al2, al3;
        ldsm4(sb + PJ_XHI + loffA + (uint32_t)(ks * 32), ah0, ah1, ah2, ah3);
        ldsm4(sb + PJ_XLO + loffA + (uint32_t)(ks * 32), al0, al1, al2, al3);
        #pragma unroll
        for (int np = 0; np < 4; np++) {
            uint32_t b0, b1, b2, b3, e0, e1, e2, e3;
            uint32_t off = loffB + (uint32_t)(np * 32 + ks * 16 * WST);
            ldsm4t(sb + PJ_WHI + off, b0, b1, b2, b3);
            ldsm4t(sb + PJ_WLO + off, e0, e1, e2, e3);
            float* ca = c[2 * np];
            float* cb = c[2 * np + 1];
            mma_bf16(ca, ah0, ah1, ah2, ah3, b0, b1);
            mma_bf16(ca, al0, al1, al2, al3, b0, b1);
            mma_bf16(ca, ah0, ah1, ah2, ah3, e0, e1);
            mma_bf16(cb, ah0, ah1, ah2, ah3, b2, b3);
            mma_bf16(cb, al0, al1, al2, al3, b2, b3);
            mma_bf16(cb, ah0, ah1, ah2, ah3, e2, e3);
        }
    }

    // ---- epilogue: bias + RoPE (+Q scale), split, store ----
    const int gr = gr0 + 16 * w + g;
    const int bb = gr >> 11, ss = gr & 2047;
    const size_t row1 = (size_t)(bb * H + hh) * SEQ + ss;
    const float QSCL = 0.08838834764831845f;
    const int dhalf = (gc0 & 127);          // 0 or 64

    #pragma unroll
    for (int nt = 0; nt < 8; nt++) {
        int d = gc0 + nt * 8 + 2 * cq;      // global col
        float2 bi = *(const float2*)&bias[d];
        float v0 = c[nt][0] + bi.x, v1 = c[nt][1] + bi.y;
        float v2 = c[nt][2] + bi.x, v3 = c[nt][3] + bi.y;
        int dp = (dhalf >> 1) + nt * 4 + cq;    // dpair within head (0..63)
        if (which < 2) {
            float2 t1 = g_rope[ss * 64 + dp];
            float2 t2 = g_rope[(ss + 8) * 64 + dp];
            float o0 = v0 * t1.x - v1 * t1.y;
            float o1 = v1 * t1.x + v0 * t1.y;
            float o2 = v2 * t2.x - v3 * t2.y;
            float o3 = v3 * t2.x + v2 * t2.y;
            v0 = o0; v1 = o1; v2 = o2; v3 = o3;
            if (which == 0) { v0 *= QSCL; v1 *= QSCL; v2 *= QSCL; v3 *= QSCL; }
        }
        uint32_t h, lo;
        packsplit(v0, v1, h, lo);
        OH[row1 * 64 + dp] = h;
        OL[row1 * 64 + dp] = lo;
        packsplit(v2, v3, h, lo);
        OH[(row1 + 8) * 64 + dp] = h;
        OL[(row1 + 8) * 64 + dp] = lo;
    }
}

// ------------------------------------------------------------------
// Kernel 2: causal flash attention (HMMA hi/lo) with 3-stage
// cp.async pipeline — ONE barrier per tile.
// ------------------------------------------------------------------
#define KVSTRIDE 272
#define OFF_KH 0
#define OFF_KL (64 * KVSTRIDE)
#define OFF_VH (2 * 64 * KVSTRIDE)
#define OFF_VL (3 * 64 * KVSTRIDE)
#define STAGE   (4 * 64 * KVSTRIDE)      // 69632 B
#define ATTN_SMEM (3 * STAGE)            // 208896 B

__device__ __forceinline__ void cp_tile(uint32_t dstbase, int tid, int bh, int kt)
{
    size_t srcbase = ((size_t)bh * SEQ + (size_t)kt * 64) * 16;   // uint4 units
    const uint4* kh4 = (const uint4*)g_khi + srcbase;
    const uint4* kl4 = (const uint4*)g_klo + srcbase;
    const uint4* vh4 = (const uint4*)g_vhi + srcbase;
    const uint4* vl4 = (const uint4*)g_vlo + srcbase;
    #pragma unroll
    for (int i = 0; i < 4; i++) {
        int x = tid + i * 256;
        int row = x >> 4, c = x & 15;
        uint32_t doff = (uint32_t)(row * KVSTRIDE + c * 16);
        int sidx = row * 16 + c;
        cp16(dstbase + OFF_KH + doff, kh4 + sidx);
        cp16(dstbase + OFF_KL + doff, kl4 + sidx);
        cp16(dstbase + OFF_VH + doff, vh4 + sidx);
        cp16(dstbase + OFF_VL + doff, vl4 + sidx);
    }
}

__global__ __launch_bounds__(256, 1) void attn_kernel()
{
    extern __shared__ char smem[];
    const uint32_t sb = smem_u32(smem);
    const int tid  = threadIdx.x;
    const int w    = tid >> 5;
    const int lane = tid & 31;
    const int bh   = blockIdx.y;
    const int qt   = 15 - (int)blockIdx.x;

    const int g  = lane >> 2;
    const int cq = lane & 3;
    const int nkt = 2 * qt + 2;          // always >= 2

    // prologue: prefetch tiles 0 and 1
    cp_tile(sb, tid, bh, 0);
    CP_COMMIT();
    cp_tile(sb + STAGE, tid, bh, 1);
    CP_COMMIT();

    uint32_t qh[8][4], ql[8][4];
    {
        const uint32_t* Qh32 = (const uint32_t*)g_qhi;
        const uint32_t* Ql32 = (const uint32_t*)g_qlo;
        size_t rowA = (size_t)bh * SEQ + qt * 128 + 16 * w + g;
        size_t rowB = rowA + 8;
        #pragma unroll
        for (int j = 0; j < 8; j++) {
            int cA = (cq << 1) + 16 * j;
            size_t iA = rowA * 64 + (cA >> 1);
            size_t iB = rowB * 64 + (cA >> 1);
            qh[j][0] = Qh32[iA];     qh[j][1] = Qh32[iB];
            qh[j][2] = Qh32[iA + 4]; qh[j][3] = Qh32[iB + 4];
            ql[j][0] = Ql32[iA];     ql[j][1] = Ql32[iB];
            ql[j][2] = Ql32[iA + 4]; ql[j][3] = Ql32[iB + 4];
        }
    }

    const uint32_t loffK = (uint32_t)((lane & 7) * KVSTRIDE + (lane >> 3) * 16);
    const uint32_t loffV = (uint32_t)((lane & 7) * KVSTRIDE + ((lane >> 3) & 1) * 8 * KVSTRIDE
                                      + (lane >> 4) * 16);

    float o[16][4];
    #pragma unroll
    for (int n = 0; n < 16; n++)
        #pragma unroll
        for (int i = 0; i < 4; i++) o[n][i] = 0.f;
    float l_a = 0.f, l_b = 0.f;

    const int rowAg = qt * 128 + 16 * w + g;

    int st = 0;     // stage of tile kt
    for (int kt = 0; kt < nkt; kt++) {
        // wait for tile kt's data (allow the in-flight next-group if any)
        if (kt < nkt - 1) { CP_WAIT(1); } else { CP_WAIT(0); }
        __syncthreads();   // publish cp.async data + all warps done with stage (kt-1)%3

        // prefetch tile kt+2 into stage (kt+2)%3 (its last readers passed the barrier above)
        if (kt + 2 < nkt) {
            int st2 = st + 2; if (st2 >= 3) st2 -= 3;
            cp_tile(sb + (uint32_t)(st2 * STAGE), tid, bh, kt + 2);
            CP_COMMIT();
        }

        const uint32_t cb = sb + (uint32_t)(st * STAGE);

        // ---- S = Q K^T (3-product hi/lo) ----
        float sfrag[8][4];
        #pragma unroll
        for (int nt = 0; nt < 8; nt++) {
            float* c = sfrag[nt];
            c[0] = c[1] = c[2] = c[3] = 0.f;
            uint32_t baseH = cb + OFF_KH + (uint32_t)(nt * 8 * KVSTRIDE) + loffK;
            uint32_t baseL = cb + OFF_KL + (uint32_t)(nt * 8 * KVSTRIDE) + loffK;
            #pragma unroll
            for (int kk = 0; kk < 4; kk++) {
                uint32_t h0, h1, h2, h3, e0, e1, e2, e3;
                ldsm4(baseH + (uint32_t)(kk * 64), h0, h1, h2, h3);
                ldsm4(baseL + (uint32_t)(kk * 64), e0, e1, e2, e3);
                int j = 2 * kk;
                mma_bf16(c, qh[j][0], qh[j][1], qh[j][2], qh[j][3], h0, h1);
                mma_bf16(c, qh[j+1][0], qh[j+1][1], qh[j+1][2], qh[j+1][3], h2, h3);
                mma_bf16(c, ql[j][0], ql[j][1], ql[j][2], ql[j][3], h0, h1);
                mma_bf16(c, ql[j+1][0], ql[j+1][1], ql[j+1][2], ql[j+1][3], h2, h3);
                mma_bf16(c, qh[j][0], qh[j][1], qh[j][2], qh[j][3], e0, e1);
                mma_bf16(c, qh[j+1][0], qh[j+1][1], qh[j+1][2], qh[j+1][3], e2, e3);
            }
        }

        // ---- softmax + causal mask ----
        const bool diag = (kt >= 2 * qt);
        const int colb = kt * 64 + 2 * cq;
        float lsa = 0.f, lsb = 0.f;
        #pragma unroll
        for (int nt = 0; nt < 8; nt++) {
            float* c = sfrag[nt];
            float p0 = __expf(c[0]);
            float p1 = __expf(c[1]);
            float p2 = __expf(c[2]);
            float p3 = __expf(c[3]);
            if (diag) {
                int cc = colb + 8 * nt;
                if (cc     > rowAg)     p0 = 0.f;
                if (cc + 1 > rowAg)     p1 = 0.f;
                if (cc     > rowAg + 8) p2 = 0.f;
                if (cc + 1 > rowAg + 8) p3 = 0.f;
            }
            c[0] = p0; c[1] = p1; c[2] = p2; c[3] = p3;
            lsa += p0 + p1;
            lsb += p2 + p3;
        }
        l_a += lsa;
        l_b += lsb;

        uint32_t ah[4][4], al[4][4];
        #pragma unroll
        for (int ks = 0; ks < 4; ks++) {
            packsplit(sfrag[2*ks][0],   sfrag[2*ks][1],   ah[ks][0], al[ks][0]);
            packsplit(sfrag[2*ks][2],   sfrag[2*ks][3],   ah[ks][1], al[ks][1]);
            packsplit(sfrag[2*ks+1][0], sfrag[2*ks+1][1], ah[ks][2], al[ks][2]);
            packsplit(sfrag[2*ks+1][2], sfrag[2*ks+1][3], ah[ks][3], al[ks][3]);
        }

        // ---- O += P V (3-product hi/lo) ----
        #pragma unroll
        for (int np = 0; np < 8; np++) {
            uint32_t baseH = cb + OFF_VH + (uint32_t)(np * 32) + loffV;
            uint32_t baseL = cb + OFF_VL + (uint32_t)(np * 32) + loffV;
            float* oa = o[2 * np];
            float* ob = o[2 * np + 1];
            #pragma unroll
            for (int ks = 0; ks < 4; ks++) {
                uint32_t h0, h1, h2, h3, e0, e1, e2, e3;
                ldsm4t(baseH + (uint32_t)(ks * 16 * KVSTRIDE), h0, h1, h2, h3);
                ldsm4t(baseL + (uint32_t)(ks * 16 * KVSTRIDE), e0, e1, e2, e3);
                mma_bf16(oa, ah[ks][0], ah[ks][1], ah[ks][2], ah[ks][3], h0, h1);
                mma_bf16(ob, ah[ks][0], ah[ks][1], ah[ks][2], ah[ks][3], h2, h3);
                mma_bf16(oa, al[ks][0], al[ks][1], al[ks][2], al[ks][3], h0, h1);
                mma_bf16(ob, al[ks][0], al[ks][1], al[ks][2], al[ks][3], h2, h3);
                mma_bf16(oa, ah[ks][0], ah[ks][1], ah[ks][2], ah[ks][3], e0, e1);
                mma_bf16(ob, ah[ks][0], ah[ks][1], ah[ks][2], ah[ks][3], e2, e3);
            }
        }

        st++; if (st >= 3) st = 0;
    }

    l_a += __shfl_xor_sync(0xffffffffu, l_a, 1);
    l_a += __shfl_xor_sync(0xffffffffu, l_a, 2);
    l_b += __shfl_xor_sync(0xffffffffu, l_b, 1);
    l_b += __shfl_xor_sync(0xffffffffu, l_b, 2);
    float inva = 1.f / l_a;
    float invb = 1.f / l_b;

    {
        uint32_t* OH = (uint32_t*)g_ohi;
        uint32_t* OL = (uint32_t*)g_olo;
        size_t rowA = (size_t)bh * SEQ + qt * 128 + 16 * w + g;
        size_t b1 = rowA * 64 + cq;
        size_t b2 = (rowA + 8) * 64 + cq;
        #pragma unroll
        for (int n = 0; n < 16; n++) {
            uint32_t h, lo;
            packsplit(o[n][0] * inva, o[n][1] * inva, h, lo);
            OH[b1 + 4 * n] = h; OL[b1 + 4 * n] = lo;
            packsplit(o[n][2] * invb, o[n][3] * invb, h, lo);
            OH[b2 + 4 * n] = h; OL[b2 + 4 * n] = lo;
        }
    }
}

// ------------------------------------------------------------------
// Kernel 3: output projection with HMMA. CTA = 64 rows x 64 cols,
// 2 CTAs/SM. Warps: 4 m-warps x 2 n-warps (16r x 32c each).
// ------------------------------------------------------------------
#define OP_AHI 0
#define OP_ALO 17408
#define OP_WHI 34816
#define OP_WLO 53248
#define OPROJ_SMEM 71680

__global__ __launch_bounds__(256, 2) void oproj_kernel(
    const float* __restrict__ Wo, const float* __restrict__ bo,
    float* __restrict__ out)
{
    extern __shared__ char smem[];
    const uint32_t sb = smem_u32(smem);
    const int tid = threadIdx.x;
    const int gc0 = (int)blockIdx.x * 64;
    const int gr0 = (int)blockIdx.y * 64;
    const int bb = gr0 >> 11, ss0 = gr0 & 2047;

    const int w    = tid >> 5;
    const int mw   = w & 3;              // 0..3 (16-row slice)
    const int nw   = w >> 2;             // 0..1 (32-col slice)
    const int lane = tid & 31;
    const int g    = lane >> 2;
    const int cq   = lane & 3;

    const uint32_t loffA = (uint32_t)((16 * mw + (lane & 15)) * PST + (lane >> 4) * 16);
    const uint32_t loffB = (uint32_t)((lane & 7) * WST + ((lane >> 3) & 1) * 8 * WST
                                      + (lane >> 4) * 16 + nw * 64);

    float c[4][4];
    #pragma unroll
    for (int n = 0; n < 4; n++) { c[n][0] = c[n][1] = c[n][2] = c[n][3] = 0.f; }

    for (int kc = 0; kc < 8; kc++) {
        if (kc) __syncthreads();
        // stage A (attn out hi/lo) for head kc: 64 rows x 128 d
        {
            const uint4* Ah = (const uint4*)g_ohi + ((size_t)(bb * H + kc) * SEQ + ss0) * 16;
            const uint4* Al = (const uint4*)g_olo + ((size_t)(bb * H + kc) * SEQ + ss0) * 16;
            #pragma unroll
            for (int i = 0; i < 4; i++) {
                int idx = tid + i * 256;
                int r = idx >> 4, q = idx & 15;
                *(uint4*)(smem + OP_AHI + r * PST + q * 16) = Ah[r * 16 + q];
                *(uint4*)(smem + OP_ALO + r * PST + q * 16) = Al[r * 16 + q];
            }
        }
        // stage Wo chunk [k=128][n=64]
        #pragma unroll
        for (int i = 0; i < 8; i++) {
            int idx = tid + i * 256;
            int k = idx >> 4, ng = (idx & 15) << 2;
            float4 t = *(const float4*)&Wo[(size_t)(kc * 128 + k) * DM + gc0 + ng];
            uint2 h2, l2;
            split4(t.x, t.y, t.z, t.w, h2, l2);
            *(uint2*)(smem + OP_WHI + k * WST + ng * 2) = h2;
            *(uint2*)(smem + OP_WLO + k * WST + ng * 2) = l2;
        }
        __syncthreads();

        #pragma unroll
        for (int ks = 0; ks < 8; ks++) {
            uint32_t ah0, ah1, ah2, ah3, al0, al1, al2, al3;
            ldsm4(sb + OP_AHI + loffA + (uint32_t)(ks * 32), ah0, ah1, ah2, ah3);
            ldsm4(sb + OP_ALO + loffA + (uint32_t)(ks * 32), al0, al1, al2, al3);
            #pragma unroll
            for (int np = 0; np < 2; np++) {
                uint32_t b0, b1, b2, b3, e0, e1, e2, e3;
                uint32_t off = loffB + (uint32_t)(np * 32 + ks * 16 * WST);
                ldsm4t(sb + OP_WHI + off, b0, b1, b2, b3);
                ldsm4t(sb + OP_WLO + off, e0, e1, e2, e3);
                float* ca = c[2 * np];
                float* cb = c[2 * np + 1];
                mma_bf16(ca, ah0, ah1, ah2, ah3, b0, b1);
                mma_bf16(ca, al0, al1, al2, al3, b0, b1);
                mma_bf16(ca, ah0, ah1, ah2, ah3, e0, e1);
                mma_bf16(cb, ah0, ah1, ah2, ah3, b2, b3);
                mma_bf16(cb, al0, al1, al2, al3, b2, b3);
                mma_bf16(cb, ah0, ah1, ah2, ah3, e2, e3);
            }
        }
    }

    const int r1 = gr0 + 16 * mw + g;
    #pragma unroll
    for (int nt = 0; nt < 4; nt++) {
        int col = gc0 + nw * 32 + nt * 8 + 2 * cq;
        float2 bi = *(const float2*)&bo[col];
        *(float2*)&out[(size_t)r1 * DM + col] =
            make_float2(c[nt][0] + bi.x, c[nt][1] + bi.y);
        *(float2*)&out[(size_t)(r1 + 8) * DM + col] =
            make_float2(c[nt][2] + bi.x, c[nt][3] + bi.y);
    }
}

// ------------------------------------------------------------------
extern "C" void kernel_launch(void* const* d_in, const int* in_sizes, int n_in,
                              void* d_out, int out_size)
{
    const float* query = (const float*)d_in[0];
    const float* key   = (const float*)d_in[1];
    const float* value = (const float*)d_in[2];
    // d_in[3] = mask (tril, analytic)
    const float* Wq = (const float*)d_in[4];
    const float* bq = (const float*)d_in[5];
    const float* Wk = (const float*)d_in[6];
    const float* bk = (const float*)d_in[7];
    const float* Wv = (const float*)d_in[8];
    const float* bv = (const float*)d_in[9];
    const float* Wo = (const float*)d_in[10];
    const float* bo = (const float*)d_in[11];
    float* out = (float*)d_out;

    cudaFuncSetAttribute(proj_kernel, cudaFuncAttributeMaxDynamicSharedMemorySize, PROJ_SMEM);
    cudaFuncSetAttribute(attn_kernel, cudaFuncAttributeMaxDynamicSharedMemorySize, ATTN_SMEM);
    cudaFuncSetAttribute(oproj_kernel, cudaFuncAttributeMaxDynamicSharedMemorySize, OPROJ_SMEM);

    rope_table_kernel<<<512, 256>>>();
    proj_kernel<<<dim3(16, 64, 3), 256, PROJ_SMEM>>>(query, key, value,
                                                     Wq, bq, Wk, bk, Wv, bv);
    attn_kernel<<<dim3(16, 32), 256, ATTN_SMEM>>>();
    oproj_kernel<<<dim3(2, 128), 256, OPROJ_SMEM>>>(Wo, bo, out);
}